// round 1
// baseline (speedup 1.0000x reference)
#include <cuda_runtime.h>

#define N_NODES 10000
#define N_EDGES 320000
#define HID 256
#define L_LEN 140
#define C_IN 5
#define C_MID 64
#define IN_FEATS (C_MID * L_LEN)   // 8960
#define EPS 1e-5f

// d_out layout: [out (N*2)][cnn1 (N*64*140)][cnn2 (N*64*140)][fin (N*256)]
#define CNN1_OFF (N_NODES * 2)
#define CNN2_OFF (CNN1_OFF + N_NODES * C_MID * L_LEN)
#define FIN_OFF  (CNN2_OFF + N_NODES * C_MID * L_LEN)

// ---------------- scratch (static device memory; no allocs) ----------------
__device__ float g_h [N_NODES * HID];
__device__ float g_h2[N_NODES * HID];
__device__ float g_hn[N_NODES * HID];
__device__ float g_hs[N_NODES * HID];
__device__ float g_z [N_NODES * C_MID];
__device__ float g_sum[HID];
__device__ float g_sq [HID];
__device__ float g_denom[N_NODES];
__device__ int   g_deg[N_NODES];
__device__ int   g_off[N_NODES + 1];
__device__ int   g_pos[N_NODES];
__device__ int   g_csr[N_EDGES];

// ---------------- small utility kernels ----------------
__global__ void zero_stats_kernel() {
    int t = threadIdx.x;           // 256 threads
    g_sum[t] = 0.f;
    g_sq[t]  = 0.f;
}

__global__ void zero_deg_kernel() {
    int i = blockIdx.x * blockDim.x + threadIdx.x;
    if (i < N_NODES) g_deg[i] = 0;
}

// ---------------- conv1: (N,5,140) x (64,5) -> (N,64,140) pre-BN ----------------
__global__ __launch_bounds__(256) void conv1_kernel(
    const float* __restrict__ x, const float* __restrict__ w,
    const float* __restrict__ bias, float* __restrict__ out)
{
    __shared__ float sx[C_IN * L_LEN];
    __shared__ float sw[C_MID * C_IN];
    __shared__ float sb[C_MID];
    int n = blockIdx.x, t = threadIdx.x;
    for (int i = t; i < C_IN * L_LEN; i += 256) sx[i] = x[(size_t)n * C_IN * L_LEN + i];
    for (int i = t; i < C_MID * C_IN; i += 256) sw[i] = w[i];
    if (t < C_MID) sb[t] = bias[t];
    __syncthreads();
    for (int idx = t; idx < C_MID * L_LEN; idx += 256) {
        int o = idx / L_LEN, l = idx % L_LEN;
        float acc = sb[o];
#pragma unroll
        for (int c = 0; c < C_IN; c++) acc += sx[c * L_LEN + l] * sw[o * C_IN + c];
        out[(size_t)n * IN_FEATS + idx] = acc;
    }
}

// ---------------- per-channel stats over (N, L): warp per row ----------------
__global__ void chan_stats_kernel(const float* __restrict__ x) {
    int gw    = (blockIdx.x * blockDim.x + threadIdx.x) >> 5;
    int lane  = threadIdx.x & 31;
    int nwrps = (gridDim.x * blockDim.x) >> 5;
    for (int row = gw; row < N_NODES * C_MID; row += nwrps) {
        const float* p = x + (size_t)row * L_LEN;
        float s = 0.f, q = 0.f;
        for (int i = lane; i < L_LEN; i += 32) { float v = p[i]; s += v; q += v * v; }
#pragma unroll
        for (int o = 16; o > 0; o >>= 1) {
            s += __shfl_down_sync(0xffffffffu, s, o);
            q += __shfl_down_sync(0xffffffffu, q, o);
        }
        if (lane == 0) {
            int ch = row % C_MID;
            atomicAdd(&g_sum[ch], s);
            atomicAdd(&g_sq[ch],  q);
        }
    }
}

// ---------------- channel BN + relu (+ optional residual) in-place ----------------
__global__ void bn_chan_apply_kernel(
    float* __restrict__ x, const float* __restrict__ res,
    const float* __restrict__ gam, const float* __restrict__ bet)
{
    const float invc = 1.0f / ((float)N_NODES * L_LEN);
    int total = N_NODES * C_MID * L_LEN;
    for (int idx = blockIdx.x * blockDim.x + threadIdx.x; idx < total;
         idx += gridDim.x * blockDim.x) {
        int ch = (idx / L_LEN) % C_MID;
        float m   = g_sum[ch] * invc;
        float var = g_sq[ch] * invc - m * m;
        float v = (x[idx] - m) * rsqrtf(var + EPS) * gam[ch] + bet[ch];
        v = fmaxf(v, 0.f);
        if (res) v += res[idx];
        x[idx] = v;
    }
}

// ---------------- conv2: (N,64,140) x (64,64) -> (N,64,140) pre-BN ----------------
// block per node; threads 16(l-groups) x 16(o-groups); 4x4 register tile
__global__ __launch_bounds__(256) void conv2_kernel(
    const float* __restrict__ in, const float* __restrict__ w,
    const float* __restrict__ bias, float* __restrict__ out)
{
    __shared__ float sx[32 * L_LEN + 64];   // half the channels + OOB pad
    __shared__ float swT[64 * 64];          // transposed: swT[c*64+o]
    __shared__ float sb[64];
    int n = blockIdx.x, t = threadIdx.x;
    for (int i = t; i < 64 * 64; i += 256) {
        int o = i >> 6, c = i & 63;
        swT[c * 64 + o] = w[i];
    }
    if (t < 64) { sb[t] = bias[t]; sx[32 * L_LEN + t] = 0.f; }
    int tx = t & 15, ty = t >> 4;
    float acc[3][4][4];
#pragma unroll
    for (int a = 0; a < 3; a++)
#pragma unroll
        for (int j = 0; j < 4; j++)
#pragma unroll
            for (int i = 0; i < 4; i++) acc[a][j][i] = 0.f;

    for (int cp = 0; cp < 2; cp++) {
        __syncthreads();
        for (int i = t; i < 32 * L_LEN; i += 256)
            sx[i] = in[(size_t)n * IN_FEATS + cp * 32 * L_LEN + i];
        __syncthreads();
#pragma unroll 4
        for (int cc = 0; cc < 32; cc++) {
            float wv[4];
            *(float4*)wv = *(const float4*)&swT[(cp * 32 + cc) * 64 + ty * 4];
#pragma unroll
            for (int lp = 0; lp < 3; lp++) {
                float xv[4];
                *(float4*)xv = *(const float4*)&sx[cc * L_LEN + lp * 64 + tx * 4];
#pragma unroll
                for (int j = 0; j < 4; j++)
#pragma unroll
                    for (int i = 0; i < 4; i++)
                        acc[lp][j][i] += wv[j] * xv[i];
            }
        }
    }
    // store
#pragma unroll
    for (int lp = 0; lp < 3; lp++) {
        int l0 = lp * 64 + tx * 4;
        if (l0 >= L_LEN) continue;     // only lp==2, tx>=3
#pragma unroll
        for (int j = 0; j < 4; j++) {
            int o = ty * 4 + j;
            float4 v;
            v.x = acc[lp][j][0] + sb[o];
            v.y = acc[lp][j][1] + sb[o];
            v.z = acc[lp][j][2] + sb[o];
            v.w = acc[lp][j][3] + sb[o];
            *(float4*)&out[(size_t)n * IN_FEATS + o * L_LEN + l0] = v;
        }
    }
}

// ---------------- degree / CSR build ----------------
__global__ void deg_kernel(const int* __restrict__ edges) {
    int e = blockIdx.x * blockDim.x + threadIdx.x;
    if (e < N_EDGES) atomicAdd(&g_deg[edges[2 * e + 1]], 1);
}

__global__ __launch_bounds__(1024) void scan_kernel() {
    __shared__ int s[1024];
    const int CHUNK = 10;                    // 1024*10 >= N_NODES
    int t = threadIdx.x;
    int base = t * CHUNK;
    int loc[CHUNK];
    int sum = 0;
#pragma unroll
    for (int i = 0; i < CHUNK; i++) {
        int v = (base + i < N_NODES) ? g_deg[base + i] : 0;
        loc[i] = sum; sum += v;
    }
    s[t] = sum;
    __syncthreads();
    for (int d = 1; d < 1024; d <<= 1) {
        int v = (t >= d) ? s[t - d] : 0;
        __syncthreads();
        s[t] += v;
        __syncthreads();
    }
    int prev = t ? s[t - 1] : 0;
#pragma unroll
    for (int i = 0; i < CHUNK; i++) {
        int n = base + i;
        if (n < N_NODES) {
            int o = prev + loc[i];
            g_off[n] = o; g_pos[n] = o;
            g_denom[n] = (float)max(g_deg[n], 1);
        }
    }
    if (t == 1023) g_off[N_NODES] = s[1023];
}

__global__ void csr_fill_kernel(const int* __restrict__ edges) {
    int e = blockIdx.x * blockDim.x + threadIdx.x;
    if (e < N_EDGES) {
        int sN = edges[2 * e], d = edges[2 * e + 1];
        int idx = atomicAdd(&g_pos[d], 1);
        g_csr[idx] = sN;
    }
}

// ---------------- generic fp32 GEMM: C[MxNc] = A[MxK] @ B[KxNc] ----------------
// 128x128 tile, BK=8, 256 threads, 8x8 per thread (split 4+4 to dodge bank conflicts)
__global__ __launch_bounds__(256) void gemm128_kernel(
    const float* __restrict__ A, const float* __restrict__ B,
    float* __restrict__ C, int M, int Nc, int K)
{
    __shared__ float As[8][132];
    __shared__ float Bs[8][132];
    int tid = threadIdx.x;
    int m0 = blockIdx.y * 128, n0 = blockIdx.x * 128;
    int tx = tid & 15, ty = tid >> 4;
    float acc[8][8];
#pragma unroll
    for (int i = 0; i < 8; i++)
#pragma unroll
        for (int j = 0; j < 8; j++) acc[i][j] = 0.f;

    int a_row = tid >> 1, a_col = (tid & 1) * 4;
    int b_row = tid >> 5, b_col = (tid & 31) * 4;
    bool a_ok = (m0 + a_row) < M;
    const float* Abase = A + (size_t)(m0 + a_row) * K + a_col;
    int bc = n0 + b_col;
    bool b_ok = bc < Nc;
    const float* Bbase = B + bc;

    for (int k0 = 0; k0 < K; k0 += 8) {
        float4 av = a_ok ? *(const float4*)(Abase + k0) : make_float4(0, 0, 0, 0);
        float4 bv = b_ok ? *(const float4*)(Bbase + (size_t)(k0 + b_row) * Nc)
                         : make_float4(0, 0, 0, 0);
        __syncthreads();
        As[a_col + 0][a_row] = av.x;
        As[a_col + 1][a_row] = av.y;
        As[a_col + 2][a_row] = av.z;
        As[a_col + 3][a_row] = av.w;
        *(float4*)&Bs[b_row][b_col] = bv;
        __syncthreads();
#pragma unroll
        for (int kk = 0; kk < 8; kk++) {
            float a[8], b[8];
            *(float4*)&a[0] = *(const float4*)&As[kk][ty * 4];
            *(float4*)&a[4] = *(const float4*)&As[kk][64 + ty * 4];
            *(float4*)&b[0] = *(const float4*)&Bs[kk][tx * 4];
            *(float4*)&b[4] = *(const float4*)&Bs[kk][64 + tx * 4];
#pragma unroll
            for (int i = 0; i < 8; i++)
#pragma unroll
                for (int j = 0; j < 8; j++) acc[i][j] += a[i] * b[j];
        }
    }
#pragma unroll
    for (int bi = 0; bi < 2; bi++)
#pragma unroll
        for (int i = 0; i < 4; i++) {
            int r = m0 + bi * 64 + ty * 4 + i;
            if (r >= M) continue;
#pragma unroll
            for (int bj = 0; bj < 2; bj++) {
                int c = n0 + bj * 64 + tx * 4;
                if (c >= Nc) continue;
                float4 v;
                v.x = acc[bi * 4 + i][bj * 4 + 0];
                v.y = acc[bi * 4 + i][bj * 4 + 1];
                v.z = acc[bi * 4 + i][bj * 4 + 2];
                v.w = acc[bi * 4 + i][bj * 4 + 3];
                *(float4*)&C[(size_t)r * Nc + c] = v;
            }
        }
}

// ---------------- neighbor gather (CSR) + combine: h2 = hs + neigh/denom + b ----------------
__global__ __launch_bounds__(256) void neigh_combine_kernel(
    const float* __restrict__ hn, const float* __restrict__ hs,
    const float* __restrict__ bias, float* __restrict__ h2)
{
    int n = blockIdx.x, t = threadIdx.x;
    __shared__ int sidx[256];
    int s0 = g_off[n], s1 = g_off[n + 1];
    float acc = 0.f;
    for (int base = s0; base < s1; base += 256) {
        int cnt = min(256, s1 - base);
        __syncthreads();
        if (t < cnt) sidx[t] = g_csr[base + t];
        __syncthreads();
        for (int j = 0; j < cnt; j++) acc += hn[(size_t)sidx[j] * HID + t];
    }
    h2[(size_t)n * HID + t] = hs[(size_t)n * HID + t] + acc / g_denom[n] + bias[t];
}

// ---------------- per-column stats over N rows (blockDim == cols) ----------------
__global__ void col_stats_kernel(const float* __restrict__ x, int rows) {
    int c = threadIdx.x, cols = blockDim.x;
    float s = 0.f, q = 0.f;
    for (int r = blockIdx.x; r < rows; r += gridDim.x) {
        float v = x[(size_t)r * cols + c];
        s += v; q += v * v;
    }
    atomicAdd(&g_sum[c], s);
    atomicAdd(&g_sq[c],  q);
}

// ---------------- node BN + optional residual + relu ----------------
__global__ void bn_apply_kernel(
    const float* __restrict__ x, const float* __restrict__ pre,
    float* __restrict__ outp, float* __restrict__ aux,
    const float* __restrict__ gam, const float* __restrict__ bet)
{
    const float invn = 1.0f / (float)N_NODES;
    int total = N_NODES * HID;
    for (int idx = blockIdx.x * blockDim.x + threadIdx.x; idx < total;
         idx += gridDim.x * blockDim.x) {
        int c = idx & (HID - 1);
        float m   = g_sum[c] * invn;
        float var = g_sq[c] * invn - m * m;
        float v = (x[idx] - m) * rsqrtf(var + EPS) * gam[c] + bet[c];
        if (pre) v += pre[idx];
        v = fmaxf(v, 0.f);
        outp[idx] = v;
        if (aux) aux[idx] = v;
    }
}

// ---------------- MLP head: bn(relu) of z then @ w2 + b2 ----------------
__global__ __launch_bounds__(128) void mlp_out_kernel(
    const float* __restrict__ z, const float* __restrict__ gam,
    const float* __restrict__ bet, const float* __restrict__ w2,
    const float* __restrict__ b2, float* __restrict__ out)
{
    __shared__ float sm[64], si[64], sg[64], sb[64], sw[128], sb2[2];
    int t = threadIdx.x;
    if (t < 64) {
        float m   = g_sum[t] / (float)N_NODES;
        float var = g_sq[t] / (float)N_NODES - m * m;
        sm[t] = m;
        si[t] = rsqrtf(var + EPS);
        sg[t] = gam[t];
        sb[t] = bet[t];
    }
    if (t < 128) sw[t] = w2[t];
    if (t < 2)   sb2[t] = b2[t];
    __syncthreads();
    int n = blockIdx.x * 128 + t;
    if (n < N_NODES) {
        float a0 = sb2[0], a1 = sb2[1];
        const float* zr = z + (size_t)n * 64;
#pragma unroll
        for (int j = 0; j < 64; j++) {
            float v = (zr[j] - sm[j]) * si[j] * sg[j] + sb[j];
            v = fmaxf(v, 0.f);
            a0 += v * sw[2 * j];
            a1 += v * sw[2 * j + 1];
        }
        out[2 * n]     = a0;
        out[2 * n + 1] = a1;
    }
}

// ---------------- host ----------------
extern "C" void kernel_launch(void* const* d_in, const int* in_sizes, int n_in,
                              void* d_out, int out_size)
{
    const float* inputs  = (const float*)d_in[0];
    const float* conv1_w = (const float*)d_in[1];
    const float* conv1_b = (const float*)d_in[2];
    const float* bn_c1_g = (const float*)d_in[3];
    const float* bn_c1_b = (const float*)d_in[4];
    const float* conv2_w = (const float*)d_in[5];
    const float* conv2_b = (const float*)d_in[6];
    const float* bn_c2_g = (const float*)d_in[7];
    const float* bn_c2_b = (const float*)d_in[8];
    const float* ws0     = (const float*)d_in[9];
    const float* wn0     = (const float*)d_in[10];
    const float* b0      = (const float*)d_in[11];
    const float* ws_rest = (const float*)d_in[12];
    const float* wn_rest = (const float*)d_in[13];
    const float* b_rest  = (const float*)d_in[14];
    const float* bn_g    = (const float*)d_in[15];
    const float* bn_b    = (const float*)d_in[16];
    const float* mlp_w1  = (const float*)d_in[17];
    // d_in[18] = mlp_b1 : constant shift, cancels exactly inside batchnorm
    const float* mlp_bn_g = (const float*)d_in[19];
    const float* mlp_bn_b = (const float*)d_in[20];
    const float* mlp_w2   = (const float*)d_in[21];
    const float* mlp_b2   = (const float*)d_in[22];
    const int*   edges    = (const int*)d_in[23];

    float* out  = (float*)d_out;
    float* cnn1 = out + CNN1_OFF;
    float* cnn2 = out + CNN2_OFF;
    float* fin  = out + FIN_OFF;

    float *hb, *h2b, *hnb, *hsb, *zb;
    cudaGetSymbolAddress((void**)&hb,  g_h);
    cudaGetSymbolAddress((void**)&h2b, g_h2);
    cudaGetSymbolAddress((void**)&hnb, g_hn);
    cudaGetSymbolAddress((void**)&hsb, g_hs);
    cudaGetSymbolAddress((void**)&zb,  g_z);

    // ---- CNN front-end ----
    zero_stats_kernel<<<1, 256>>>();
    conv1_kernel<<<N_NODES, 256>>>(inputs, conv1_w, conv1_b, cnn1);
    chan_stats_kernel<<<2048, 256>>>(cnn1);
    bn_chan_apply_kernel<<<8192, 256>>>(cnn1, nullptr, bn_c1_g, bn_c1_b);

    zero_stats_kernel<<<1, 256>>>();
    conv2_kernel<<<N_NODES, 256>>>(cnn1, conv2_w, conv2_b, cnn2);
    chan_stats_kernel<<<2048, 256>>>(cnn2);
    bn_chan_apply_kernel<<<8192, 256>>>(cnn2, cnn1, bn_c2_g, bn_c2_b);

    // ---- degree + CSR ----
    zero_deg_kernel<<<(N_NODES + 255) / 256, 256>>>();
    deg_kernel<<<(N_EDGES + 255) / 256, 256>>>(edges);
    scan_kernel<<<1, 1024>>>();
    csr_fill_kernel<<<(N_EDGES + 255) / 256, 256>>>(edges);

    // ---- 4 GraphSAGE layers ----
    for (int l = 0; l < 4; l++) {
        const float* A  = (l == 0) ? cnn2 : hb;
        int K           = (l == 0) ? IN_FEATS : HID;
        const float* wn = (l == 0) ? wn0 : wn_rest + (size_t)(l - 1) * HID * HID;
        const float* ws = (l == 0) ? ws0 : ws_rest + (size_t)(l - 1) * HID * HID;
        const float* bb = (l == 0) ? b0  : b_rest + (size_t)(l - 1) * HID;

        dim3 grid(2, 79);   // ceil(256/128) x ceil(10000/128)
        gemm128_kernel<<<grid, 256>>>(A, wn, hnb, N_NODES, HID, K);
        gemm128_kernel<<<grid, 256>>>(A, ws, hsb, N_NODES, HID, K);

        neigh_combine_kernel<<<N_NODES, 256>>>(hnb, hsb, bb, h2b);

        zero_stats_kernel<<<1, 256>>>();
        col_stats_kernel<<<512, HID>>>(h2b, N_NODES);
        bn_apply_kernel<<<2560, 256>>>(
            h2b, (l > 0) ? hb : nullptr, hb, (l == 3) ? fin : nullptr,
            bn_g + (size_t)l * HID, bn_b + (size_t)l * HID);
    }

    // ---- MLP head ----
    {
        dim3 grid(1, 79);
        gemm128_kernel<<<grid, 256>>>(hb, mlp_w1, zb, N_NODES, C_MID, HID);
        zero_stats_kernel<<<1, 256>>>();
        col_stats_kernel<<<2048, C_MID>>>(zb, N_NODES);
        mlp_out_kernel<<<(N_NODES + 127) / 128, 128>>>(
            zb, mlp_bn_g, mlp_bn_b, mlp_w2, mlp_b2, out);
    }
}

// round 2
// speedup vs baseline: 1.1121x; 1.1121x over previous
#include <cuda_runtime.h>

#define N_NODES 10000
#define N_EDGES 320000
#define HID 256
#define L_LEN 140
#define C_IN 5
#define C_MID 64
#define IN_FEATS (C_MID * L_LEN)   // 8960
#define EPS 1e-5f

// d_out layout: [out (N*2)][cnn1 (N*64*140)][cnn2 (N*64*140)][fin (N*256)]
#define CNN1_OFF (N_NODES * 2)
#define CNN2_OFF (CNN1_OFF + N_NODES * C_MID * L_LEN)
#define FIN_OFF  (CNN2_OFF + N_NODES * C_MID * L_LEN)

typedef unsigned long long ull;

// ---------------- f32x2 helpers (Blackwell packed fp32 pipe) ----------------
__device__ __forceinline__ ull pkdup(float x) {
    unsigned int u = __float_as_uint(x);
    ull r;
    asm("mov.b64 %0, {%1, %1};" : "=l"(r) : "r"(u));
    return r;
}
__device__ __forceinline__ void ffma2(ull& d, ull a, ull b) {
    asm("fma.rn.f32x2 %0, %1, %2, %0;" : "+l"(d) : "l"(a), "l"(b));
}
__device__ __forceinline__ void unpk(ull v, float& lo, float& hi) {
    unsigned int a, b;
    asm("mov.b64 {%0, %1}, %2;" : "=r"(a), "=r"(b) : "l"(v));
    lo = __uint_as_float(a);
    hi = __uint_as_float(b);
}
__device__ __forceinline__ void lds2(ull& p0, ull& p1, unsigned int addr) {
    asm volatile("ld.shared.v2.b64 {%0, %1}, [%2];" : "=l"(p0), "=l"(p1) : "r"(addr));
}
__device__ __forceinline__ void sts64(unsigned int addr, ull v) {
    asm volatile("st.shared.b64 [%0], %1;" :: "r"(addr), "l"(v));
}

// ---------------- scratch (static device memory; no allocs) ----------------
__device__ float g_h [N_NODES * HID];
__device__ float g_h2[N_NODES * HID];
__device__ float g_hn[N_NODES * HID];
__device__ float g_hs[N_NODES * HID];
__device__ float g_z [N_NODES * C_MID];
__device__ float g_sum[HID];
__device__ float g_sq [HID];
__device__ float g_denom[N_NODES];
__device__ int   g_deg[N_NODES];
__device__ int   g_off[N_NODES + 1];
__device__ int   g_pos[N_NODES];
__device__ int   g_csr[N_EDGES];

// ---------------- small utility kernels ----------------
__global__ void zero_stats_kernel() {
    int t = threadIdx.x;           // 256 threads
    g_sum[t] = 0.f;
    g_sq[t]  = 0.f;
}

__global__ void zero_deg_kernel() {
    int i = blockIdx.x * blockDim.x + threadIdx.x;
    if (i < N_NODES) g_deg[i] = 0;
}

// ---------------- conv1: (N,5,140) x (64,5) -> (N,64,140) pre-BN ----------------
__global__ __launch_bounds__(256) void conv1_kernel(
    const float* __restrict__ x, const float* __restrict__ w,
    const float* __restrict__ bias, float* __restrict__ out)
{
    __shared__ float sx[C_IN * L_LEN];
    __shared__ float sw[C_MID * C_IN];
    __shared__ float sb[C_MID];
    int n = blockIdx.x, t = threadIdx.x;
    for (int i = t; i < C_IN * L_LEN; i += 256) sx[i] = x[(size_t)n * C_IN * L_LEN + i];
    for (int i = t; i < C_MID * C_IN; i += 256) sw[i] = w[i];
    if (t < C_MID) sb[t] = bias[t];
    __syncthreads();
    for (int idx = t; idx < C_MID * L_LEN; idx += 256) {
        int o = idx / L_LEN, l = idx % L_LEN;
        float acc = sb[o];
#pragma unroll
        for (int c = 0; c < C_IN; c++) acc += sx[c * L_LEN + l] * sw[o * C_IN + c];
        out[(size_t)n * IN_FEATS + idx] = acc;
    }
}

// ---------------- per-channel stats over (N, L): warp per row, float4 ----------------
__global__ void chan_stats_kernel(const float* __restrict__ x) {
    int gw    = (blockIdx.x * blockDim.x + threadIdx.x) >> 5;
    int lane  = threadIdx.x & 31;
    int nwrps = (gridDim.x * blockDim.x) >> 5;
    for (int row = gw; row < N_NODES * C_MID; row += nwrps) {
        const float4* p = (const float4*)(x + (size_t)row * L_LEN);   // 35 float4 per row
        float s = 0.f, q = 0.f;
        float4 v = p[lane];
        s += v.x + v.y + v.z + v.w;
        q += v.x * v.x + v.y * v.y + v.z * v.z + v.w * v.w;
        if (lane < 3) {
            v = p[lane + 32];
            s += v.x + v.y + v.z + v.w;
            q += v.x * v.x + v.y * v.y + v.z * v.z + v.w * v.w;
        }
#pragma unroll
        for (int o = 16; o > 0; o >>= 1) {
            s += __shfl_down_sync(0xffffffffu, s, o);
            q += __shfl_down_sync(0xffffffffu, q, o);
        }
        if (lane == 0) {
            int ch = row % C_MID;
            atomicAdd(&g_sum[ch], s);
            atomicAdd(&g_sq[ch],  q);
        }
    }
}

// ---------------- channel BN + relu (+ optional residual) in-place, float4 ----------------
__global__ void bn_chan_apply_kernel(
    float4* __restrict__ x, const float4* __restrict__ res,
    const float* __restrict__ gam, const float* __restrict__ bet)
{
    const float invc = 1.0f / ((float)N_NODES * L_LEN);
    const int total4 = N_NODES * C_MID * (L_LEN / 4);
    for (int idx = blockIdx.x * blockDim.x + threadIdx.x; idx < total4;
         idx += gridDim.x * blockDim.x) {
        int ch = (idx / (L_LEN / 4)) & (C_MID - 1);
        float m   = g_sum[ch] * invc;
        float var = g_sq[ch] * invc - m * m;
        float sc  = rsqrtf(var + EPS) * gam[ch];
        float sh  = bet[ch] - m * sc;
        float4 v = x[idx];
        v.x = fmaxf(v.x * sc + sh, 0.f);
        v.y = fmaxf(v.y * sc + sh, 0.f);
        v.z = fmaxf(v.z * sc + sh, 0.f);
        v.w = fmaxf(v.w * sc + sh, 0.f);
        if (res) {
            float4 r = res[idx];
            v.x += r.x; v.y += r.y; v.z += r.z; v.w += r.w;
        }
        x[idx] = v;
    }
}

// ---------------- conv2: (N,64,140) x (64,64) -> (N,64,140) pre-BN (f32x2) ----------------
__global__ __launch_bounds__(256) void conv2_kernel(
    const float* __restrict__ in, const float* __restrict__ w,
    const float* __restrict__ bias, float* __restrict__ out)
{
    __shared__ float sx[32 * L_LEN + 64];   // half the channels + OOB pad
    __shared__ float swT[64 * 64];          // transposed: swT[c*64+o]
    __shared__ float sb[64];
    int n = blockIdx.x, t = threadIdx.x;
    for (int i = t; i < 64 * 64; i += 256) {
        int o = i >> 6, c = i & 63;
        swT[c * 64 + o] = w[i];
    }
    if (t < 64) { sb[t] = bias[t]; sx[32 * L_LEN + t] = 0.f; }
    int tx = t & 15, ty = t >> 4;
    unsigned int sx_base = (unsigned int)__cvta_generic_to_shared(sx) + tx * 16;

    ull acc[3][4][2];
#pragma unroll
    for (int a = 0; a < 3; a++)
#pragma unroll
        for (int j = 0; j < 4; j++) { acc[a][j][0] = 0ull; acc[a][j][1] = 0ull; }

    for (int cp = 0; cp < 2; cp++) {
        __syncthreads();
        for (int i = t; i < 32 * L_LEN; i += 256)
            sx[i] = in[(size_t)n * IN_FEATS + cp * 32 * L_LEN + i];
        __syncthreads();
#pragma unroll 4
        for (int cc = 0; cc < 32; cc++) {
            float wv[4];
            *(float4*)wv = *(const float4*)&swT[(cp * 32 + cc) * 64 + ty * 4];
            ull w2[4];
#pragma unroll
            for (int j = 0; j < 4; j++) w2[j] = pkdup(wv[j]);
#pragma unroll
            for (int lp = 0; lp < 3; lp++) {
                ull x0, x1;
                lds2(x0, x1, sx_base + cc * (L_LEN * 4) + lp * 256);
#pragma unroll
                for (int j = 0; j < 4; j++) {
                    ffma2(acc[lp][j][0], w2[j], x0);
                    ffma2(acc[lp][j][1], w2[j], x1);
                }
            }
        }
    }
    // store
#pragma unroll
    for (int lp = 0; lp < 3; lp++) {
        int l0 = lp * 64 + tx * 4;
        if (l0 >= L_LEN) continue;     // only lp==2, tx>=3
#pragma unroll
        for (int j = 0; j < 4; j++) {
            int o = ty * 4 + j;
            float4 v;
            unpk(acc[lp][j][0], v.x, v.y);
            unpk(acc[lp][j][1], v.z, v.w);
            v.x += sb[o]; v.y += sb[o]; v.z += sb[o]; v.w += sb[o];
            *(float4*)&out[(size_t)n * IN_FEATS + o * L_LEN + l0] = v;
        }
    }
}

// ---------------- degree / CSR build ----------------
__global__ void deg_kernel(const int* __restrict__ edges) {
    int e = blockIdx.x * blockDim.x + threadIdx.x;
    if (e < N_EDGES) atomicAdd(&g_deg[edges[2 * e + 1]], 1);
}

__global__ __launch_bounds__(1024) void scan_kernel() {
    __shared__ int s[1024];
    const int CHUNK = 10;                    // 1024*10 >= N_NODES
    int t = threadIdx.x;
    int base = t * CHUNK;
    int loc[CHUNK];
    int sum = 0;
#pragma unroll
    for (int i = 0; i < CHUNK; i++) {
        int v = (base + i < N_NODES) ? g_deg[base + i] : 0;
        loc[i] = sum; sum += v;
    }
    s[t] = sum;
    __syncthreads();
    for (int d = 1; d < 1024; d <<= 1) {
        int v = (t >= d) ? s[t - d] : 0;
        __syncthreads();
        s[t] += v;
        __syncthreads();
    }
    int prev = t ? s[t - 1] : 0;
#pragma unroll
    for (int i = 0; i < CHUNK; i++) {
        int n = base + i;
        if (n < N_NODES) {
            int o = prev + loc[i];
            g_off[n] = o; g_pos[n] = o;
            g_denom[n] = (float)max(g_deg[n], 1);
        }
    }
    if (t == 1023) g_off[N_NODES] = s[1023];
}

__global__ void csr_fill_kernel(const int* __restrict__ edges) {
    int e = blockIdx.x * blockDim.x + threadIdx.x;
    if (e < N_EDGES) {
        int sN = edges[2 * e], d = edges[2 * e + 1];
        int idx = atomicAdd(&g_pos[d], 1);
        g_csr[idx] = sN;
    }
}

// ---------------- dual fp32 GEMM (f32x2): C{0,1}[MxNc] = A[MxK] @ B{0,1}[KxNc] ----------------
// 128x128 tile, BK=8, 256 threads, 8x(4x f32x2) per thread.
// A duplicated in SMEM so {a,a} pairs come from one ld.shared.v2.b64.
__global__ __launch_bounds__(256, 2) void gemm2_kernel(
    const float* __restrict__ A,
    const float* __restrict__ B0, const float* __restrict__ B1,
    float* __restrict__ C0, float* __restrict__ C1,
    int M, int Nc, int K, int nxHalf)
{
    __shared__ float As[8][264];   // duplicated m-dim: As[kk][2m]=As[kk][2m+1]=a
    __shared__ float Bs[8][132];
    int bx = blockIdx.x;
    const float* B = B0;
    float* C = C0;
    if (bx >= nxHalf) { B = B1; C = C1; bx -= nxHalf; }
    int tid = threadIdx.x;
    int m0 = blockIdx.y * 128, n0 = bx * 128;
    int tx = tid & 15, ty = tid >> 4;

    ull acc[8][4];
#pragma unroll
    for (int i = 0; i < 8; i++)
#pragma unroll
        for (int j = 0; j < 4; j++) acc[i][j] = 0ull;

    int a_row = tid >> 1, a_col = (tid & 1) * 4;
    int b_row = tid >> 5, b_col = (tid & 31) * 4;
    bool a_ok = (m0 + a_row) < M;
    bool b_ok = (n0 + b_col) < Nc;
    const float* Abase = A + (size_t)(m0 + a_row) * K + a_col;
    const float* Bbase = B + n0 + b_col;

    unsigned int as0 = (unsigned int)__cvta_generic_to_shared(As);
    unsigned int bs0 = (unsigned int)__cvta_generic_to_shared(Bs);
    unsigned int as_w = as0 + a_col * (264 * 4) + a_row * 8;   // As[a_col+i][2*a_row]
    unsigned int as_r = as0 + ty * 32;                          // rows ty*4.. pairs
    unsigned int bs_r = bs0 + tx * 16;

    for (int k0 = 0; k0 < K; k0 += 8) {
        float4 av = a_ok ? *(const float4*)(Abase + k0) : make_float4(0, 0, 0, 0);
        float4 bv = b_ok ? *(const float4*)(Bbase + (size_t)(k0 + b_row) * Nc)
                         : make_float4(0, 0, 0, 0);
        __syncthreads();
        sts64(as_w + 0 * 1056, pkdup(av.x));
        sts64(as_w + 1 * 1056, pkdup(av.y));
        sts64(as_w + 2 * 1056, pkdup(av.z));
        sts64(as_w + 3 * 1056, pkdup(av.w));
        *(float4*)&Bs[b_row][b_col] = bv;
        __syncthreads();
#pragma unroll
        for (int kk = 0; kk < 8; kk++) {
            ull a2[8], b2[4];
            unsigned int ar = as_r + kk * 1056;
            unsigned int br = bs_r + kk * 528;
            lds2(a2[0], a2[1], ar);
            lds2(a2[2], a2[3], ar + 16);
            lds2(a2[4], a2[5], ar + 512);
            lds2(a2[6], a2[7], ar + 528);
            lds2(b2[0], b2[1], br);
            lds2(b2[2], b2[3], br + 256);
#pragma unroll
            for (int i = 0; i < 8; i++)
#pragma unroll
                for (int j = 0; j < 4; j++) ffma2(acc[i][j], a2[i], b2[j]);
        }
    }
#pragma unroll
    for (int bi = 0; bi < 2; bi++)
#pragma unroll
        for (int i = 0; i < 4; i++) {
            int r = m0 + bi * 64 + ty * 4 + i;
            if (r >= M) continue;
            int i8 = bi * 4 + i;
#pragma unroll
            for (int bj = 0; bj < 2; bj++) {
                int c = n0 + bj * 64 + tx * 4;
                if (c >= Nc) continue;
                float4 v;
                unpk(acc[i8][2 * bj + 0], v.x, v.y);
                unpk(acc[i8][2 * bj + 1], v.z, v.w);
                *(float4*)&C[(size_t)r * Nc + c] = v;
            }
        }
}

// ---------------- neighbor gather (CSR) + combine: h2 = hs + neigh/denom + b ----------------
__global__ __launch_bounds__(256) void neigh_combine_kernel(
    const float* __restrict__ hn, const float* __restrict__ hs,
    const float* __restrict__ bias, float* __restrict__ h2)
{
    int n = blockIdx.x, t = threadIdx.x;
    __shared__ int sidx[256];
    int s0 = g_off[n], s1 = g_off[n + 1];
    float acc = 0.f;
    for (int base = s0; base < s1; base += 256) {
        int cnt = min(256, s1 - base);
        __syncthreads();
        if (t < cnt) sidx[t] = g_csr[base + t];
        __syncthreads();
        for (int j = 0; j < cnt; j++) acc += hn[(size_t)sidx[j] * HID + t];
    }
    h2[(size_t)n * HID + t] = hs[(size_t)n * HID + t] + acc / g_denom[n] + bias[t];
}

// ---------------- per-column stats over N rows (blockDim == cols) ----------------
__global__ void col_stats_kernel(const float* __restrict__ x, int rows) {
    int c = threadIdx.x, cols = blockDim.x;
    float s = 0.f, q = 0.f;
    for (int r = blockIdx.x; r < rows; r += gridDim.x) {
        float v = x[(size_t)r * cols + c];
        s += v; q += v * v;
    }
    atomicAdd(&g_sum[c], s);
    atomicAdd(&g_sq[c],  q);
}

// ---------------- node BN + optional residual + relu ----------------
__global__ void bn_apply_kernel(
    const float* __restrict__ x, const float* __restrict__ pre,
    float* __restrict__ outp, float* __restrict__ aux,
    const float* __restrict__ gam, const float* __restrict__ bet)
{
    const float invn = 1.0f / (float)N_NODES;
    int total = N_NODES * HID;
    for (int idx = blockIdx.x * blockDim.x + threadIdx.x; idx < total;
         idx += gridDim.x * blockDim.x) {
        int c = idx & (HID - 1);
        float m   = g_sum[c] * invn;
        float var = g_sq[c] * invn - m * m;
        float v = (x[idx] - m) * rsqrtf(var + EPS) * gam[c] + bet[c];
        if (pre) v += pre[idx];
        v = fmaxf(v, 0.f);
        outp[idx] = v;
        if (aux) aux[idx] = v;
    }
}

// ---------------- MLP head: bn(relu) of z then @ w2 + b2 ----------------
__global__ __launch_bounds__(128) void mlp_out_kernel(
    const float* __restrict__ z, const float* __restrict__ gam,
    const float* __restrict__ bet, const float* __restrict__ w2,
    const float* __restrict__ b2, float* __restrict__ out)
{
    __shared__ float sm[64], si[64], sg[64], sb[64], sw[128], sb2[2];
    int t = threadIdx.x;
    if (t < 64) {
        float m   = g_sum[t] / (float)N_NODES;
        float var = g_sq[t] / (float)N_NODES - m * m;
        sm[t] = m;
        si[t] = rsqrtf(var + EPS);
        sg[t] = gam[t];
        sb[t] = bet[t];
    }
    if (t < 128) sw[t] = w2[t];
    if (t < 2)   sb2[t] = b2[t];
    __syncthreads();
    int n = blockIdx.x * 128 + t;
    if (n < N_NODES) {
        float a0 = sb2[0], a1 = sb2[1];
        const float* zr = z + (size_t)n * 64;
#pragma unroll
        for (int j = 0; j < 64; j++) {
            float v = (zr[j] - sm[j]) * si[j] * sg[j] + sb[j];
            v = fmaxf(v, 0.f);
            a0 += v * sw[2 * j];
            a1 += v * sw[2 * j + 1];
        }
        out[2 * n]     = a0;
        out[2 * n + 1] = a1;
    }
}

// ---------------- host ----------------
extern "C" void kernel_launch(void* const* d_in, const int* in_sizes, int n_in,
                              void* d_out, int out_size)
{
    const float* inputs  = (const float*)d_in[0];
    const float* conv1_w = (const float*)d_in[1];
    const float* conv1_b = (const float*)d_in[2];
    const float* bn_c1_g = (const float*)d_in[3];
    const float* bn_c1_b = (const float*)d_in[4];
    const float* conv2_w = (const float*)d_in[5];
    const float* conv2_b = (const float*)d_in[6];
    const float* bn_c2_g = (const float*)d_in[7];
    const float* bn_c2_b = (const float*)d_in[8];
    const float* ws0     = (const float*)d_in[9];
    const float* wn0     = (const float*)d_in[10];
    const float* b0      = (const float*)d_in[11];
    const float* ws_rest = (const float*)d_in[12];
    const float* wn_rest = (const float*)d_in[13];
    const float* b_rest  = (const float*)d_in[14];
    const float* bn_g    = (const float*)d_in[15];
    const float* bn_b    = (const float*)d_in[16];
    const float* mlp_w1  = (const float*)d_in[17];
    // d_in[18] = mlp_b1 : constant shift, cancels exactly inside batchnorm
    const float* mlp_bn_g = (const float*)d_in[19];
    const float* mlp_bn_b = (const float*)d_in[20];
    const float* mlp_w2   = (const float*)d_in[21];
    const float* mlp_b2   = (const float*)d_in[22];
    const int*   edges    = (const int*)d_in[23];

    float* out  = (float*)d_out;
    float* cnn1 = out + CNN1_OFF;
    float* cnn2 = out + CNN2_OFF;
    float* fin  = out + FIN_OFF;

    float *hb, *h2b, *hnb, *hsb, *zb;
    cudaGetSymbolAddress((void**)&hb,  g_h);
    cudaGetSymbolAddress((void**)&h2b, g_h2);
    cudaGetSymbolAddress((void**)&hnb, g_hn);
    cudaGetSymbolAddress((void**)&hsb, g_hs);
    cudaGetSymbolAddress((void**)&zb,  g_z);

    // ---- CNN front-end ----
    zero_stats_kernel<<<1, 256>>>();
    conv1_kernel<<<N_NODES, 256>>>(inputs, conv1_w, conv1_b, cnn1);
    chan_stats_kernel<<<2048, 256>>>(cnn1);
    bn_chan_apply_kernel<<<8192, 256>>>((float4*)cnn1, nullptr, bn_c1_g, bn_c1_b);

    zero_stats_kernel<<<1, 256>>>();
    conv2_kernel<<<N_NODES, 256>>>(cnn1, conv2_w, conv2_b, cnn2);
    chan_stats_kernel<<<2048, 256>>>(cnn2);
    bn_chan_apply_kernel<<<8192, 256>>>((float4*)cnn2, (const float4*)cnn1, bn_c2_g, bn_c2_b);

    // ---- degree + CSR ----
    zero_deg_kernel<<<(N_NODES + 255) / 256, 256>>>();
    deg_kernel<<<(N_EDGES + 255) / 256, 256>>>(edges);
    scan_kernel<<<1, 1024>>>();
    csr_fill_kernel<<<(N_EDGES + 255) / 256, 256>>>(edges);

    // ---- 4 GraphSAGE layers ----
    for (int l = 0; l < 4; l++) {
        const float* A  = (l == 0) ? cnn2 : hb;
        int K           = (l == 0) ? IN_FEATS : HID;
        const float* wn = (l == 0) ? wn0 : wn_rest + (size_t)(l - 1) * HID * HID;
        const float* ws = (l == 0) ? ws0 : ws_rest + (size_t)(l - 1) * HID * HID;
        const float* bb = (l == 0) ? b0  : b_rest + (size_t)(l - 1) * HID;

        dim3 grid(4, 79);   // 2 n-blocks x {ws, wn}  x  ceil(10000/128)
        gemm2_kernel<<<grid, 256>>>(A, ws, wn, hsb, hnb, N_NODES, HID, K, 2);

        neigh_combine_kernel<<<N_NODES, 256>>>(hnb, hsb, bb, h2b);

        zero_stats_kernel<<<1, 256>>>();
        col_stats_kernel<<<512, HID>>>(h2b, N_NODES);
        bn_apply_kernel<<<2560, 256>>>(
            h2b, (l > 0) ? hb : nullptr, hb, (l == 3) ? fin : nullptr,
            bn_g + (size_t)l * HID, bn_b + (size_t)l * HID);
    }

    // ---- MLP head ----
    {
        dim3 grid(1, 79);
        gemm2_kernel<<<grid, 256>>>(hb, mlp_w1, mlp_w1, zb, zb, N_NODES, C_MID, HID, 1);
        zero_stats_kernel<<<1, 256>>>();
        col_stats_kernel<<<2048, C_MID>>>(zb, N_NODES);
        mlp_out_kernel<<<(N_NODES + 127) / 128, 128>>>(
            zb, mlp_bn_g, mlp_bn_b, mlp_w2, mlp_b2, out);
    }
}

// round 4
// speedup vs baseline: 1.7589x; 1.5816x over previous
#include <cuda_runtime.h>
#include <cuda_bf16.h>

#define N_NODES 10000
#define N_EDGES 320000
#define HID 256
#define L_LEN 140
#define C_IN 5
#define C_MID 64
#define IN_FEATS (C_MID * L_LEN)   // 8960
#define EPS 1e-5f

// d_out layout: [out (N*2)][cnn1 (N*64*140)][cnn2 (N*64*140)][fin (N*256)]
#define CNN1_OFF (N_NODES * 2)
#define CNN2_OFF (CNN1_OFF + N_NODES * C_MID * L_LEN)
#define FIN_OFF  (CNN2_OFF + N_NODES * C_MID * L_LEN)

// weight (transposed, split) buffer: layer0 512x8960, layers1-3 512x256
#define W_L0_ELEMS (512 * IN_FEATS)
#define W_REST_ELEMS (512 * HID)
#define W_TOTAL (W_L0_ELEMS + 3 * W_REST_ELEMS)

typedef unsigned long long ull;

// ---------------- f32x2 helpers ----------------
__device__ __forceinline__ ull pkdup(float x) {
    unsigned int u = __float_as_uint(x);
    ull r;
    asm("mov.b64 %0, {%1, %1};" : "=l"(r) : "r"(u));
    return r;
}
__device__ __forceinline__ void ffma2(ull& d, ull a, ull b) {
    asm("fma.rn.f32x2 %0, %1, %2, %0;" : "+l"(d) : "l"(a), "l"(b));
}
__device__ __forceinline__ void unpk(ull v, float& lo, float& hi) {
    unsigned int a, b;
    asm("mov.b64 {%0, %1}, %2;" : "=r"(a), "=r"(b) : "l"(v));
    lo = __uint_as_float(a);
    hi = __uint_as_float(b);
}
__device__ __forceinline__ void lds2w(ull& p0, ull& p1, unsigned int addr) {
    asm volatile("ld.shared.v2.b64 {%0, %1}, [%2];" : "=l"(p0), "=l"(p1) : "r"(addr));
}
__device__ __forceinline__ void sts64(unsigned int addr, ull v) {
    asm volatile("st.shared.b64 [%0], %1;" :: "r"(addr), "l"(v));
}
__device__ __forceinline__ unsigned int smem_u32(const void* p) {
    unsigned int a;
    asm("{ .reg .u64 t; cvta.to.shared.u64 t, %1; cvt.u32.u64 %0, t; }" : "=r"(a) : "l"(p));
    return a;
}

// ---------------- mma.sync / ldmatrix / cp.async helpers ----------------
#define LDSM4(r, addr) \
    asm volatile("ldmatrix.sync.aligned.m8n8.x4.shared.b16 {%0,%1,%2,%3}, [%4];" \
                 : "=r"((r)[0]), "=r"((r)[1]), "=r"((r)[2]), "=r"((r)[3]) : "r"(addr))

#define MMA16816(d, a, b0, b1) \
    asm volatile("mma.sync.aligned.m16n8k16.row.col.f32.bf16.bf16.f32 " \
                 "{%0,%1,%2,%3}, {%4,%5,%6,%7}, {%8,%9}, {%0,%1,%2,%3};" \
                 : "+f"((d)[0]), "+f"((d)[1]), "+f"((d)[2]), "+f"((d)[3]) \
                 : "r"((a)[0]), "r"((a)[1]), "r"((a)[2]), "r"((a)[3]), \
                   "r"(b0), "r"(b1))

#define CP16(daddr, gptr) \
    asm volatile("cp.async.cg.shared.global [%0], [%1], 16;" \
                 :: "r"(daddr), "l"(gptr))

// ---------------- scratch (static device memory; no allocs) ----------------
__device__ float g_h [N_NODES * HID];
__device__ float g_h2[N_NODES * HID];
__device__ float g_hn[N_NODES * HID];
__device__ float g_hs[N_NODES * HID];
__device__ float g_z [N_NODES * C_MID];
__device__ float g_sum[HID];
__device__ float g_sq [HID];
__device__ float g_denom[N_NODES];
__device__ int   g_deg[N_NODES];
__device__ int   g_off[N_NODES + 1];
__device__ int   g_pos[N_NODES];
__device__ int   g_csr[N_EDGES];
__device__ __nv_bfloat16 g_Ahi[N_NODES * IN_FEATS];
__device__ __nv_bfloat16 g_Alo[N_NODES * IN_FEATS];
__device__ __nv_bfloat16 g_Whi[W_TOTAL];
__device__ __nv_bfloat16 g_Wlo[W_TOTAL];

// ---------------- small utility kernels ----------------
__global__ void zero_stats_kernel() {
    int t = threadIdx.x;
    g_sum[t] = 0.f;
    g_sq[t]  = 0.f;
}
__global__ void zero_deg_kernel() {
    int i = blockIdx.x * blockDim.x + threadIdx.x;
    if (i < N_NODES) g_deg[i] = 0;
}

// ---------------- conv1 ----------------
__global__ __launch_bounds__(256) void conv1_kernel(
    const float* __restrict__ x, const float* __restrict__ w,
    const float* __restrict__ bias, float* __restrict__ out)
{
    __shared__ float sx[C_IN * L_LEN];
    __shared__ float sw[C_MID * C_IN];
    __shared__ float sb[C_MID];
    int n = blockIdx.x, t = threadIdx.x;
    for (int i = t; i < C_IN * L_LEN; i += 256) sx[i] = x[(size_t)n * C_IN * L_LEN + i];
    for (int i = t; i < C_MID * C_IN; i += 256) sw[i] = w[i];
    if (t < C_MID) sb[t] = bias[t];
    __syncthreads();
    for (int idx = t; idx < C_MID * L_LEN; idx += 256) {
        int o = idx / L_LEN, l = idx % L_LEN;
        float acc = sb[o];
#pragma unroll
        for (int c = 0; c < C_IN; c++) acc += sx[c * L_LEN + l] * sw[o * C_IN + c];
        out[(size_t)n * IN_FEATS + idx] = acc;
    }
}

// ---------------- per-channel stats over (N, L): warp per row, float4 ----------------
__global__ void chan_stats_kernel(const float* __restrict__ x) {
    int gw    = (blockIdx.x * blockDim.x + threadIdx.x) >> 5;
    int lane  = threadIdx.x & 31;
    int nwrps = (gridDim.x * blockDim.x) >> 5;
    for (int row = gw; row < N_NODES * C_MID; row += nwrps) {
        const float4* p = (const float4*)(x + (size_t)row * L_LEN);
        float s = 0.f, q = 0.f;
        float4 v = p[lane];
        s += v.x + v.y + v.z + v.w;
        q += v.x * v.x + v.y * v.y + v.z * v.z + v.w * v.w;
        if (lane < 3) {
            v = p[lane + 32];
            s += v.x + v.y + v.z + v.w;
            q += v.x * v.x + v.y * v.y + v.z * v.z + v.w * v.w;
        }
#pragma unroll
        for (int o = 16; o > 0; o >>= 1) {
            s += __shfl_down_sync(0xffffffffu, s, o);
            q += __shfl_down_sync(0xffffffffu, q, o);
        }
        if (lane == 0) {
            int ch = row % C_MID;
            atomicAdd(&g_sum[ch], s);
            atomicAdd(&g_sq[ch],  q);
        }
    }
}

// ---------------- channel BN + relu (+residual) in-place; optional bf16 hi/lo split out ----------------
__global__ void bn_chan_apply_kernel(
    float4* __restrict__ x, const float4* __restrict__ res,
    const float* __restrict__ gam, const float* __restrict__ bet,
    __nv_bfloat162* __restrict__ ahi, __nv_bfloat162* __restrict__ alo)
{
    const float invc = 1.0f / ((float)N_NODES * L_LEN);
    const int total4 = N_NODES * C_MID * (L_LEN / 4);
    for (int idx = blockIdx.x * blockDim.x + threadIdx.x; idx < total4;
         idx += gridDim.x * blockDim.x) {
        int ch = (idx / (L_LEN / 4)) & (C_MID - 1);
        float m   = g_sum[ch] * invc;
        float var = g_sq[ch] * invc - m * m;
        float sc  = rsqrtf(var + EPS) * gam[ch];
        float sh  = bet[ch] - m * sc;
        float4 v = x[idx];
        v.x = fmaxf(v.x * sc + sh, 0.f);
        v.y = fmaxf(v.y * sc + sh, 0.f);
        v.z = fmaxf(v.z * sc + sh, 0.f);
        v.w = fmaxf(v.w * sc + sh, 0.f);
        if (res) {
            float4 r = res[idx];
            v.x += r.x; v.y += r.y; v.z += r.z; v.w += r.w;
        }
        x[idx] = v;
        if (ahi) {
            __nv_bfloat16 hx = __float2bfloat16_rn(v.x);
            __nv_bfloat16 hy = __float2bfloat16_rn(v.y);
            __nv_bfloat16 hz = __float2bfloat16_rn(v.z);
            __nv_bfloat16 hw = __float2bfloat16_rn(v.w);
            ahi[2 * idx]     = __nv_bfloat162{hx, hy};
            ahi[2 * idx + 1] = __nv_bfloat162{hz, hw};
            alo[2 * idx] = __nv_bfloat162{
                __float2bfloat16_rn(v.x - __bfloat162float(hx)),
                __float2bfloat16_rn(v.y - __bfloat162float(hy))};
            alo[2 * idx + 1] = __nv_bfloat162{
                __float2bfloat16_rn(v.z - __bfloat162float(hz)),
                __float2bfloat16_rn(v.w - __bfloat162float(hw))};
        }
    }
}

// ---------------- conv2 (f32x2) ----------------
__global__ __launch_bounds__(256) void conv2_kernel(
    const float* __restrict__ in, const float* __restrict__ w,
    const float* __restrict__ bias, float* __restrict__ out)
{
    __shared__ float sx[32 * L_LEN + 64];
    __shared__ float swT[64 * 64];
    __shared__ float sb[64];
    int n = blockIdx.x, t = threadIdx.x;
    for (int i = t; i < 64 * 64; i += 256) {
        int o = i >> 6, c = i & 63;
        swT[c * 64 + o] = w[i];
    }
    if (t < 64) { sb[t] = bias[t]; sx[32 * L_LEN + t] = 0.f; }
    int tx = t & 15, ty = t >> 4;
    unsigned int sx_base = smem_u32(sx) + tx * 16;

    ull acc[3][4][2];
#pragma unroll
    for (int a = 0; a < 3; a++)
#pragma unroll
        for (int j = 0; j < 4; j++) { acc[a][j][0] = 0ull; acc[a][j][1] = 0ull; }

    for (int cp = 0; cp < 2; cp++) {
        __syncthreads();
        for (int i = t; i < 32 * L_LEN; i += 256)
            sx[i] = in[(size_t)n * IN_FEATS + cp * 32 * L_LEN + i];
        __syncthreads();
#pragma unroll 4
        for (int cc = 0; cc < 32; cc++) {
            float wv[4];
            *(float4*)wv = *(const float4*)&swT[(cp * 32 + cc) * 64 + ty * 4];
            ull w2[4];
#pragma unroll
            for (int j = 0; j < 4; j++) w2[j] = pkdup(wv[j]);
#pragma unroll
            for (int lp = 0; lp < 3; lp++) {
                ull x0, x1;
                lds2w(x0, x1, sx_base + cc * (L_LEN * 4) + lp * 256);
#pragma unroll
                for (int j = 0; j < 4; j++) {
                    ffma2(acc[lp][j][0], w2[j], x0);
                    ffma2(acc[lp][j][1], w2[j], x1);
                }
            }
        }
    }
#pragma unroll
    for (int lp = 0; lp < 3; lp++) {
        int l0 = lp * 64 + tx * 4;
        if (l0 >= L_LEN) continue;
#pragma unroll
        for (int j = 0; j < 4; j++) {
            int o = ty * 4 + j;
            float4 v;
            unpk(acc[lp][j][0], v.x, v.y);
            unpk(acc[lp][j][1], v.z, v.w);
            v.x += sb[o]; v.y += sb[o]; v.z += sb[o]; v.w += sb[o];
            *(float4*)&out[(size_t)n * IN_FEATS + o * L_LEN + l0] = v;
        }
    }
}

// ---------------- degree / CSR ----------------
__global__ void deg_kernel(const int* __restrict__ edges) {
    int e = blockIdx.x * blockDim.x + threadIdx.x;
    if (e < N_EDGES) atomicAdd(&g_deg[edges[2 * e + 1]], 1);
}

__global__ __launch_bounds__(1024) void scan_kernel() {
    __shared__ int s[1024];
    const int CHUNK = 10;
    int t = threadIdx.x;
    int base = t * CHUNK;
    int loc[CHUNK];
    int sum = 0;
#pragma unroll
    for (int i = 0; i < CHUNK; i++) {
        int v = (base + i < N_NODES) ? g_deg[base + i] : 0;
        loc[i] = sum; sum += v;
    }
    s[t] = sum;
    __syncthreads();
    for (int d = 1; d < 1024; d <<= 1) {
        int v = (t >= d) ? s[t - d] : 0;
        __syncthreads();
        s[t] += v;
        __syncthreads();
    }
    int prev = t ? s[t - 1] : 0;
#pragma unroll
    for (int i = 0; i < CHUNK; i++) {
        int n = base + i;
        if (n < N_NODES) {
            int o = prev + loc[i];
            g_off[n] = o; g_pos[n] = o;
            g_denom[n] = (float)max(g_deg[n], 1);
        }
    }
    if (t == 1023) g_off[N_NODES] = s[1023];
}

__global__ void csr_fill_kernel(const int* __restrict__ edges) {
    int e = blockIdx.x * blockDim.x + threadIdx.x;
    if (e < N_EDGES) {
        int sN = edges[2 * e], d = edges[2 * e + 1];
        int idx = atomicAdd(&g_pos[d], 1);
        g_csr[idx] = sN;
    }
}

// ---------------- weight transpose + bf16 split: W[K][256]x2 -> Wcat^T[512][K] ----------------
__global__ void wsplit_kernel(const float* __restrict__ ws, const float* __restrict__ wn,
                              __nv_bfloat16* __restrict__ whi,
                              __nv_bfloat16* __restrict__ wlo, int K)
{
    __shared__ float tile[32][33];
    int k0 = blockIdx.x * 32, n0 = blockIdx.y * 32;
    int tx = threadIdx.x, ty = threadIdx.y;   // 32 x 8
#pragma unroll
    for (int r = 0; r < 32; r += 8) {
        int k = k0 + ty + r, n = n0 + tx;
        float v = (n < 256) ? ws[(size_t)k * 256 + n] : wn[(size_t)k * 256 + n - 256];
        tile[ty + r][tx] = v;
    }
    __syncthreads();
#pragma unroll
    for (int r = 0; r < 32; r += 8) {
        int n = n0 + ty + r, k = k0 + tx;
        float v = tile[tx][ty + r];
        __nv_bfloat16 h = __float2bfloat16_rn(v);
        whi[(size_t)n * K + k] = h;
        wlo[(size_t)n * K + k] = __float2bfloat16_rn(v - __bfloat162float(h));
    }
}

// ---------------- HMMA bf16 split GEMM ----------------
// CTA tile 128(M)x128(N), chunks of K=32, cp.async double buffer.
// Grid (4, 79): blockIdx.x picks 128-col slice of the 512-wide [ws | wn] weight.
// SMEM layout: row stride 64B (32 bf16), 16B-chunk XOR swizzle: chunk ^ ((row>>1)&3).
__device__ __forceinline__ unsigned int swz(unsigned int base, int row, int kc) {
    return base + row * 64 + ((kc ^ ((row >> 1) & 3)) << 4);
}

__device__ __forceinline__ void mma_issue_load(
    const __nv_bfloat16* __restrict__ Ap, const __nv_bfloat16* __restrict__ Bp,
    unsigned int sa, unsigned int sb, int m0, int n0, int k0, int K, int tid)
{
#pragma unroll
    for (int i = 0; i < 2; i++) {
        int idx = tid + i * 256;
        int row = idx >> 2, cch = idx & 3;
        int rg = m0 + row; if (rg > N_NODES - 1) rg = N_NODES - 1;
        CP16(swz(sa, row, cch), Ap + (size_t)rg * K + k0 + cch * 8);
    }
#pragma unroll
    for (int i = 0; i < 2; i++) {
        int idx = tid + i * 256;
        int row = idx >> 2, cch = idx & 3;
        CP16(swz(sb, row, cch), Bp + (size_t)(n0 + row) * K + k0 + cch * 8);
    }
    asm volatile("cp.async.commit_group;");
}

__global__ __launch_bounds__(256) void gemm_mma_kernel(
    const __nv_bfloat16* __restrict__ Ahi, const __nv_bfloat16* __restrict__ Alo,
    const __nv_bfloat16* __restrict__ Bhi, const __nv_bfloat16* __restrict__ Blo,
    float* __restrict__ Cs, float* __restrict__ Cn, int K)
{
    __shared__ __align__(1024) char AsBuf[2][8192];
    __shared__ __align__(1024) char BsBuf[2][8192];
    int tid = threadIdx.x, wid = tid >> 5, lane = tid & 31;
    int m0 = blockIdx.y * 128;
    int n0 = blockIdx.x * 128;         // 0..384 within [ws|wn]
    int wm = (wid & 3) * 32;
    int wn = (wid >> 2) * 64;

    unsigned int sa[2] = { smem_u32(AsBuf[0]), smem_u32(AsBuf[1]) };
    unsigned int sb[2] = { smem_u32(BsBuf[0]), smem_u32(BsBuf[1]) };

    const __nv_bfloat16* At[3] = {Ahi, Ahi, Alo};
    const __nv_bfloat16* Bt[3] = {Bhi, Blo, Bhi};
    const int KC = K / 32, NC = 3 * KC;

    float acc[2][8][4];
#pragma unroll
    for (int i = 0; i < 2; i++)
#pragma unroll
        for (int j = 0; j < 8; j++)
#pragma unroll
            for (int q = 0; q < 4; q++) acc[i][j][q] = 0.f;

    mma_issue_load(At[0], Bt[0], sa[0], sb[0], m0, n0, 0, K, tid);

    for (int c = 0; c < NC; c++) {
        if (c + 1 < NC) {
            int t2 = (c + 1) / KC;
            int k2 = ((c + 1) - t2 * KC) * 32;
            int s2 = (c + 1) & 1;
            mma_issue_load(At[t2], Bt[t2], sa[s2], sb[s2], m0, n0, k2, K, tid);
            asm volatile("cp.async.wait_group 1;");
        } else {
            asm volatile("cp.async.wait_group 0;");
        }
        __syncthreads();
        int s = c & 1;
        unsigned int sas = sa[s], sbs = sb[s];
#pragma unroll
        for (int ks = 0; ks < 2; ks++) {
            int kc = ks * 2 + (lane >> 4);
            unsigned int a[2][4], b[4][4];
            LDSM4(a[0], swz(sas, wm + (lane & 15), kc));
            LDSM4(a[1], swz(sas, wm + 16 + (lane & 15), kc));
#pragma unroll
            for (int j = 0; j < 4; j++)
                LDSM4(b[j], swz(sbs, wn + j * 16 + (lane & 15), kc));
#pragma unroll
            for (int mi = 0; mi < 2; mi++)
#pragma unroll
                for (int j = 0; j < 4; j++) {
                    MMA16816(acc[mi][2 * j],     a[mi], b[j][0], b[j][2]);
                    MMA16816(acc[mi][2 * j + 1], a[mi], b[j][1], b[j][3]);
                }
        }
        __syncthreads();
    }

    // epilogue
    float* Cout = (n0 < 256) ? Cs : Cn;
    int ncol0 = n0 & 255;
    int g = lane >> 2, tq = lane & 3;
#pragma unroll
    for (int mi = 0; mi < 2; mi++) {
        int r0 = m0 + wm + mi * 16 + g;
#pragma unroll
        for (int j = 0; j < 8; j++) {
            int col = ncol0 + wn + j * 8 + tq * 2;
            if (r0 < N_NODES)
                *(float2*)&Cout[(size_t)r0 * 256 + col] =
                    make_float2(acc[mi][j][0], acc[mi][j][1]);
            if (r0 + 8 < N_NODES)
                *(float2*)&Cout[(size_t)(r0 + 8) * 256 + col] =
                    make_float2(acc[mi][j][2], acc[mi][j][3]);
        }
    }
}

// ---------------- fp32 SIMT GEMM (MLP head only) ----------------
__global__ __launch_bounds__(256, 2) void gemm2_kernel(
    const float* __restrict__ A,
    const float* __restrict__ B0, const float* __restrict__ B1,
    float* __restrict__ C0, float* __restrict__ C1,
    int M, int Nc, int K, int nxHalf)
{
    __shared__ float As[8][264];
    __shared__ float Bs[8][132];
    int bx = blockIdx.x;
    const float* B = B0;
    float* C = C0;
    if (bx >= nxHalf) { B = B1; C = C1; bx -= nxHalf; }
    int tid = threadIdx.x;
    int m0 = blockIdx.y * 128, n0 = bx * 128;
    int tx = tid & 15, ty = tid >> 4;

    ull acc[8][4];
#pragma unroll
    for (int i = 0; i < 8; i++)
#pragma unroll
        for (int j = 0; j < 4; j++) acc[i][j] = 0ull;

    int a_row = tid >> 1, a_col = (tid & 1) * 4;
    int b_row = tid >> 5, b_col = (tid & 31) * 4;
    bool a_ok = (m0 + a_row) < M;
    bool b_ok = (n0 + b_col) < Nc;
    const float* Abase = A + (size_t)(m0 + a_row) * K + a_col;
    const float* Bbase = B + n0 + b_col;

    unsigned int as0 = smem_u32(As);
    unsigned int bs0 = smem_u32(Bs);
    unsigned int as_w = as0 + a_col * (264 * 4) + a_row * 8;
    unsigned int as_r = as0 + ty * 32;
    unsigned int bs_r = bs0 + tx * 16;

    for (int k0 = 0; k0 < K; k0 += 8) {
        float4 av = a_ok ? *(const float4*)(Abase + k0) : make_float4(0, 0, 0, 0);
        float4 bv = b_ok ? *(const float4*)(Bbase + (size_t)(k0 + b_row) * Nc)
                         : make_float4(0, 0, 0, 0);
        __syncthreads();
        sts64(as_w + 0 * 1056, pkdup(av.x));
        sts64(as_w + 1 * 1056, pkdup(av.y));
        sts64(as_w + 2 * 1056, pkdup(av.z));
        sts64(as_w + 3 * 1056, pkdup(av.w));
        *(float4*)&Bs[b_row][b_col] = bv;
        __syncthreads();
#pragma unroll
        for (int kk = 0; kk < 8; kk++) {
            ull a2[8], b2[4];
            unsigned int ar = as_r + kk * 1056;
            unsigned int br = bs_r + kk * 528;
            lds2w(a2[0], a2[1], ar);
            lds2w(a2[2], a2[3], ar + 16);
            lds2w(a2[4], a2[5], ar + 512);
            lds2w(a2[6], a2[7], ar + 528);
            lds2w(b2[0], b2[1], br);
            lds2w(b2[2], b2[3], br + 256);
#pragma unroll
            for (int i = 0; i < 8; i++)
#pragma unroll
                for (int j = 0; j < 4; j++) ffma2(acc[i][j], a2[i], b2[j]);
        }
    }
#pragma unroll
    for (int bi = 0; bi < 2; bi++)
#pragma unroll
        for (int i = 0; i < 4; i++) {
            int r = m0 + bi * 64 + ty * 4 + i;
            if (r >= M) continue;
            int i8 = bi * 4 + i;
#pragma unroll
            for (int bj = 0; bj < 2; bj++) {
                int c = n0 + bj * 64 + tx * 4;
                if (c >= Nc) continue;
                float4 v;
                unpk(acc[i8][2 * bj + 0], v.x, v.y);
                unpk(acc[i8][2 * bj + 1], v.z, v.w);
                *(float4*)&C[(size_t)r * Nc + c] = v;
            }
        }
}

// ---------------- neighbor gather (CSR) + combine ----------------
__global__ __launch_bounds__(256) void neigh_combine_kernel(
    const float* __restrict__ hn, const float* __restrict__ hs,
    const float* __restrict__ bias, float* __restrict__ h2)
{
    int n = blockIdx.x, t = threadIdx.x;
    __shared__ int sidx[256];
    int s0 = g_off[n], s1 = g_off[n + 1];
    float acc = 0.f;
    for (int base = s0; base < s1; base += 256) {
        int cnt = min(256, s1 - base);
        __syncthreads();
        if (t < cnt) sidx[t] = g_csr[base + t];
        __syncthreads();
        for (int j = 0; j < cnt; j++) acc += hn[(size_t)sidx[j] * HID + t];
    }
    h2[(size_t)n * HID + t] = hs[(size_t)n * HID + t] + acc / g_denom[n] + bias[t];
}

// ---------------- per-column stats ----------------
__global__ void col_stats_kernel(const float* __restrict__ x, int rows) {
    int c = threadIdx.x, cols = blockDim.x;
    float s = 0.f, q = 0.f;
    for (int r = blockIdx.x; r < rows; r += gridDim.x) {
        float v = x[(size_t)r * cols + c];
        s += v; q += v * v;
    }
    atomicAdd(&g_sum[c], s);
    atomicAdd(&g_sq[c],  q);
}

// ---------------- node BN + residual + relu; optional bf16 split out ----------------
__global__ void bn_apply_kernel(
    const float* __restrict__ x, const float* __restrict__ pre,
    float* __restrict__ outp, float* __restrict__ aux,
    const float* __restrict__ gam, const float* __restrict__ bet,
    __nv_bfloat16* __restrict__ ahi, __nv_bfloat16* __restrict__ alo)
{
    const float invn = 1.0f / (float)N_NODES;
    int total = N_NODES * HID;
    for (int idx = blockIdx.x * blockDim.x + threadIdx.x; idx < total;
         idx += gridDim.x * blockDim.x) {
        int c = idx & (HID - 1);
        float m   = g_sum[c] * invn;
        float var = g_sq[c] * invn - m * m;
        float v = (x[idx] - m) * rsqrtf(var + EPS) * gam[c] + bet[c];
        if (pre) v += pre[idx];
        v = fmaxf(v, 0.f);
        outp[idx] = v;
        if (aux) aux[idx] = v;
        if (ahi) {
            __nv_bfloat16 h = __float2bfloat16_rn(v);
            ahi[idx] = h;
            alo[idx] = __float2bfloat16_rn(v - __bfloat162float(h));
        }
    }
}

// ---------------- MLP head ----------------
__global__ __launch_bounds__(128) void mlp_out_kernel(
    const float* __restrict__ z, const float* __restrict__ gam,
    const float* __restrict__ bet, const float* __restrict__ w2,
    const float* __restrict__ b2, float* __restrict__ out)
{
    __shared__ float sm[64], si[64], sg[64], sb[64], sw[128], sb2[2];
    int t = threadIdx.x;
    if (t < 64) {
        float m   = g_sum[t] / (float)N_NODES;
        float var = g_sq[t] / (float)N_NODES - m * m;
        sm[t] = m;
        si[t] = rsqrtf(var + EPS);
        sg[t] = gam[t];
        sb[t] = bet[t];
    }
    if (t < 128) sw[t] = w2[t];
    if (t < 2)   sb2[t] = b2[t];
    __syncthreads();
    int n = blockIdx.x * 128 + t;
    if (n < N_NODES) {
        float a0 = sb2[0], a1 = sb2[1];
        const float* zr = z + (size_t)n * 64;
#pragma unroll
        for (int j = 0; j < 64; j++) {
            float v = (zr[j] - sm[j]) * si[j] * sg[j] + sb[j];
            v = fmaxf(v, 0.f);
            a0 += v * sw[2 * j];
            a1 += v * sw[2 * j + 1];
        }
        out[2 * n]     = a0;
        out[2 * n + 1] = a1;
    }
}

// ---------------- host ----------------
extern "C" void kernel_launch(void* const* d_in, const int* in_sizes, int n_in,
                              void* d_out, int out_size)
{
    const float* inputs  = (const float*)d_in[0];
    const float* conv1_w = (const float*)d_in[1];
    const float* conv1_b = (const float*)d_in[2];
    const float* bn_c1_g = (const float*)d_in[3];
    const float* bn_c1_b = (const float*)d_in[4];
    const float* conv2_w = (const float*)d_in[5];
    const float* conv2_b = (const float*)d_in[6];
    const float* bn_c2_g = (const float*)d_in[7];
    const float* bn_c2_b = (const float*)d_in[8];
    const float* ws0     = (const float*)d_in[9];
    const float* wn0     = (const float*)d_in[10];
    const float* b0      = (const float*)d_in[11];
    const float* ws_rest = (const float*)d_in[12];
    const float* wn_rest = (const float*)d_in[13];
    const float* b_rest  = (const float*)d_in[14];
    const float* bn_g    = (const float*)d_in[15];
    const float* bn_b    = (const float*)d_in[16];
    const float* mlp_w1  = (const float*)d_in[17];
    // d_in[18] = mlp_b1 : constant shift, cancels exactly inside batchnorm
    const float* mlp_bn_g = (const float*)d_in[19];
    const float* mlp_bn_b = (const float*)d_in[20];
    const float* mlp_w2   = (const float*)d_in[21];
    const float* mlp_b2   = (const float*)d_in[22];
    const int*   edges    = (const int*)d_in[23];

    float* out  = (float*)d_out;
    float* cnn1 = out + CNN1_OFF;
    float* cnn2 = out + CNN2_OFF;
    float* fin  = out + FIN_OFF;

    float *hb, *h2b, *hnb, *hsb, *zb;
    __nv_bfloat16 *ahib, *alob, *whib, *wlob;
    cudaGetSymbolAddress((void**)&hb,   g_h);
    cudaGetSymbolAddress((void**)&h2b,  g_h2);
    cudaGetSymbolAddress((void**)&hnb,  g_hn);
    cudaGetSymbolAddress((void**)&hsb,  g_hs);
    cudaGetSymbolAddress((void**)&zb,   g_z);
    cudaGetSymbolAddress((void**)&ahib, g_Ahi);
    cudaGetSymbolAddress((void**)&alob, g_Alo);
    cudaGetSymbolAddress((void**)&whib, g_Whi);
    cudaGetSymbolAddress((void**)&wlob, g_Wlo);

    // ---- weight transpose + split ----
    wsplit_kernel<<<dim3(IN_FEATS / 32, 16), dim3(32, 8)>>>(ws0, wn0, whib, wlob, IN_FEATS);
    for (int l = 1; l < 4; l++) {
        wsplit_kernel<<<dim3(HID / 32, 16), dim3(32, 8)>>>(
            ws_rest + (size_t)(l - 1) * HID * HID,
            wn_rest + (size_t)(l - 1) * HID * HID,
            whib + W_L0_ELEMS + (size_t)(l - 1) * W_REST_ELEMS,
            wlob + W_L0_ELEMS + (size_t)(l - 1) * W_REST_ELEMS, HID);
    }

    // ---- CNN front-end ----
    zero_stats_kernel<<<1, 256>>>();
    conv1_kernel<<<N_NODES, 256>>>(inputs, conv1_w, conv1_b, cnn1);
    chan_stats_kernel<<<2048, 256>>>(cnn1);
    bn_chan_apply_kernel<<<8192, 256>>>((float4*)cnn1, nullptr, bn_c1_g, bn_c1_b,
                                        nullptr, nullptr);

    zero_stats_kernel<<<1, 256>>>();
    conv2_kernel<<<N_NODES, 256>>>(cnn1, conv2_w, conv2_b, cnn2);
    chan_stats_kernel<<<2048, 256>>>(cnn2);
    bn_chan_apply_kernel<<<8192, 256>>>((float4*)cnn2, (const float4*)cnn1,
                                        bn_c2_g, bn_c2_b,
                                        (__nv_bfloat162*)ahib, (__nv_bfloat162*)alob);

    // ---- degree + CSR ----
    zero_deg_kernel<<<(N_NODES + 255) / 256, 256>>>();
    deg_kernel<<<(N_EDGES + 255) / 256, 256>>>(edges);
    scan_kernel<<<1, 1024>>>();
    csr_fill_kernel<<<(N_EDGES + 255) / 256, 256>>>(edges);

    // ---- 4 GraphSAGE layers (HMMA split-bf16 GEMMs) ----
    for (int l = 0; l < 4; l++) {
        int K = (l == 0) ? IN_FEATS : HID;
        const __nv_bfloat16* wh =
            whib + ((l == 0) ? 0 : W_L0_ELEMS + (size_t)(l - 1) * W_REST_ELEMS);
        const __nv_bfloat16* wl =
            wlob + ((l == 0) ? 0 : W_L0_ELEMS + (size_t)(l - 1) * W_REST_ELEMS);
        const float* bb = (l == 0) ? b0 : b_rest + (size_t)(l - 1) * HID;

        gemm_mma_kernel<<<dim3(4, 79), 256>>>(ahib, alob, wh, wl, hsb, hnb, K);

        neigh_combine_kernel<<<N_NODES, 256>>>(hnb, hsb, bb, h2b);

        zero_stats_kernel<<<1, 256>>>();
        col_stats_kernel<<<512, HID>>>(h2b, N_NODES);
        bn_apply_kernel<<<2560, 256>>>(
            h2b, (l > 0) ? hb : nullptr, hb, (l == 3) ? fin : nullptr,
            bn_g + (size_t)l * HID, bn_b + (size_t)l * HID,
            (l < 3) ? ahib : nullptr, (l < 3) ? alob : nullptr);
    }

    // ---- MLP head ----
    {
        dim3 grid(1, 79);
        gemm2_kernel<<<grid, 256>>>(hb, mlp_w1, mlp_w1, zb, zb, N_NODES, C_MID, HID, 1);
        zero_stats_kernel<<<1, 256>>>();
        col_stats_kernel<<<2048, C_MID>>>(zb, N_NODES);
        mlp_out_kernel<<<(N_NODES + 127) / 128, 128>>>(
            zb, mlp_bn_g, mlp_bn_b, mlp_w2, mlp_b2, out);
    }
}

// round 5
// speedup vs baseline: 2.0981x; 1.1928x over previous
#include <cuda_runtime.h>
#include <cuda_bf16.h>

#define N_NODES 10000
#define N_EDGES 320000
#define HID 256
#define L_LEN 140
#define C_IN 5
#define C_MID 64
#define IN_FEATS (C_MID * L_LEN)   // 8960
#define EPS 1e-5f

// d_out layout: [out (N*2)][cnn1 (N*64*140)][cnn2 (N*64*140)][fin (N*256)]
#define CNN1_OFF (N_NODES * 2)
#define CNN2_OFF (CNN1_OFF + N_NODES * C_MID * L_LEN)
#define FIN_OFF  (CNN2_OFF + N_NODES * C_MID * L_LEN)

// weight (transposed, split) buffer: layer0 512x8960, layers1-3 512x256
#define W_L0_ELEMS (512 * IN_FEATS)
#define W_REST_ELEMS (512 * HID)
#define W_TOTAL (W_L0_ELEMS + 3 * W_REST_ELEMS)

typedef unsigned long long ull;

// ---------------- f32x2 helpers ----------------
__device__ __forceinline__ ull pkdup(float x) {
    unsigned int u = __float_as_uint(x);
    ull r;
    asm("mov.b64 %0, {%1, %1};" : "=l"(r) : "r"(u));
    return r;
}
__device__ __forceinline__ void ffma2(ull& d, ull a, ull b) {
    asm("fma.rn.f32x2 %0, %1, %2, %0;" : "+l"(d) : "l"(a), "l"(b));
}
__device__ __forceinline__ void unpk(ull v, float& lo, float& hi) {
    unsigned int a, b;
    asm("mov.b64 {%0, %1}, %2;" : "=r"(a), "=r"(b) : "l"(v));
    lo = __uint_as_float(a);
    hi = __uint_as_float(b);
}
__device__ __forceinline__ void lds2w(ull& p0, ull& p1, unsigned int addr) {
    asm volatile("ld.shared.v2.b64 {%0, %1}, [%2];" : "=l"(p0), "=l"(p1) : "r"(addr));
}
__device__ __forceinline__ void sts64(unsigned int addr, ull v) {
    asm volatile("st.shared.b64 [%0], %1;" :: "r"(addr), "l"(v));
}
__device__ __forceinline__ unsigned int smem_u32(const void* p) {
    unsigned int a;
    asm("{ .reg .u64 t; cvta.to.shared.u64 t, %1; cvt.u32.u64 %0, t; }" : "=r"(a) : "l"(p));
    return a;
}

// ---------------- mma.sync / ldmatrix / cp.async helpers ----------------
#define LDSM4(r, addr) \
    asm volatile("ldmatrix.sync.aligned.m8n8.x4.shared.b16 {%0,%1,%2,%3}, [%4];" \
                 : "=r"((r)[0]), "=r"((r)[1]), "=r"((r)[2]), "=r"((r)[3]) : "r"(addr))

#define MMA16816(d, a, b0, b1) \
    asm volatile("mma.sync.aligned.m16n8k16.row.col.f32.bf16.bf16.f32 " \
                 "{%0,%1,%2,%3}, {%4,%5,%6,%7}, {%8,%9}, {%0,%1,%2,%3};" \
                 : "+f"((d)[0]), "+f"((d)[1]), "+f"((d)[2]), "+f"((d)[3]) \
                 : "r"((a)[0]), "r"((a)[1]), "r"((a)[2]), "r"((a)[3]), \
                   "r"(b0), "r"(b1))

#define CP16(daddr, gptr) \
    asm volatile("cp.async.cg.shared.global [%0], [%1], 16;" \
                 :: "r"(daddr), "l"(gptr))

// ---------------- scratch (static device memory; no allocs) ----------------
__device__ float g_h [N_NODES * HID];
__device__ float g_h2[N_NODES * HID];
__device__ float g_hn[N_NODES * HID];
__device__ float g_hs[N_NODES * HID];
__device__ float g_z [N_NODES * C_MID];
__device__ float g_sum[HID];
__device__ float g_sq [HID];
__device__ float g_denom[N_NODES];
__device__ int   g_deg[N_NODES];
__device__ int   g_off[N_NODES + 1];
__device__ int   g_pos[N_NODES];
__device__ int   g_csr[N_EDGES];
__device__ __nv_bfloat16 g_Ahi[N_NODES * IN_FEATS];
__device__ __nv_bfloat16 g_Alo[N_NODES * IN_FEATS];
__device__ __nv_bfloat16 g_Whi[W_TOTAL];
__device__ __nv_bfloat16 g_Wlo[W_TOTAL];

// ---------------- small utility kernels ----------------
__global__ void zero_stats_kernel() {
    int t = threadIdx.x;
    g_sum[t] = 0.f;
    g_sq[t]  = 0.f;
}
__global__ void zero_deg_kernel() {
    int i = blockIdx.x * blockDim.x + threadIdx.x;
    if (i < N_NODES) g_deg[i] = 0;
}

// ---------------- conv1 ----------------
__global__ __launch_bounds__(256) void conv1_kernel(
    const float* __restrict__ x, const float* __restrict__ w,
    const float* __restrict__ bias, float* __restrict__ out)
{
    __shared__ float sx[C_IN * L_LEN];
    __shared__ float sw[C_MID * C_IN];
    __shared__ float sb[C_MID];
    int n = blockIdx.x, t = threadIdx.x;
    for (int i = t; i < C_IN * L_LEN; i += 256) sx[i] = x[(size_t)n * C_IN * L_LEN + i];
    for (int i = t; i < C_MID * C_IN; i += 256) sw[i] = w[i];
    if (t < C_MID) sb[t] = bias[t];
    __syncthreads();
    for (int idx = t; idx < C_MID * L_LEN; idx += 256) {
        int o = idx / L_LEN, l = idx % L_LEN;
        float acc = sb[o];
#pragma unroll
        for (int c = 0; c < C_IN; c++) acc += sx[c * L_LEN + l] * sw[o * C_IN + c];
        out[(size_t)n * IN_FEATS + idx] = acc;
    }
}

// ---------------- per-channel stats over (N, L): warp per row, float4 ----------------
__global__ void chan_stats_kernel(const float* __restrict__ x) {
    int gw    = (blockIdx.x * blockDim.x + threadIdx.x) >> 5;
    int lane  = threadIdx.x & 31;
    int nwrps = (gridDim.x * blockDim.x) >> 5;
    for (int row = gw; row < N_NODES * C_MID; row += nwrps) {
        const float4* p = (const float4*)(x + (size_t)row * L_LEN);
        float s = 0.f, q = 0.f;
        float4 v = p[lane];
        s += v.x + v.y + v.z + v.w;
        q += v.x * v.x + v.y * v.y + v.z * v.z + v.w * v.w;
        if (lane < 3) {
            v = p[lane + 32];
            s += v.x + v.y + v.z + v.w;
            q += v.x * v.x + v.y * v.y + v.z * v.z + v.w * v.w;
        }
#pragma unroll
        for (int o = 16; o > 0; o >>= 1) {
            s += __shfl_down_sync(0xffffffffu, s, o);
            q += __shfl_down_sync(0xffffffffu, q, o);
        }
        if (lane == 0) {
            int ch = row % C_MID;
            atomicAdd(&g_sum[ch], s);
            atomicAdd(&g_sq[ch],  q);
        }
    }
}

// ---------------- channel BN + relu (+residual) in-place; optional bf16 hi/lo split out ----------------
__global__ void bn_chan_apply_kernel(
    float4* __restrict__ x, const float4* __restrict__ res,
    const float* __restrict__ gam, const float* __restrict__ bet,
    __nv_bfloat162* __restrict__ ahi, __nv_bfloat162* __restrict__ alo, int soff)
{
    const float invc = 1.0f / ((float)N_NODES * L_LEN);
    const int total4 = N_NODES * C_MID * (L_LEN / 4);
    for (int idx = blockIdx.x * blockDim.x + threadIdx.x; idx < total4;
         idx += gridDim.x * blockDim.x) {
        int ch = (idx / (L_LEN / 4)) & (C_MID - 1);
        float m   = g_sum[soff + ch] * invc;
        float var = g_sq[soff + ch] * invc - m * m;
        float sc  = rsqrtf(var + EPS) * gam[ch];
        float sh  = bet[ch] - m * sc;
        float4 v = x[idx];
        v.x = fmaxf(v.x * sc + sh, 0.f);
        v.y = fmaxf(v.y * sc + sh, 0.f);
        v.z = fmaxf(v.z * sc + sh, 0.f);
        v.w = fmaxf(v.w * sc + sh, 0.f);
        if (res) {
            float4 r = res[idx];
            v.x += r.x; v.y += r.y; v.z += r.z; v.w += r.w;
        }
        x[idx] = v;
        if (ahi) {
            __nv_bfloat16 hx = __float2bfloat16_rn(v.x);
            __nv_bfloat16 hy = __float2bfloat16_rn(v.y);
            __nv_bfloat16 hz = __float2bfloat16_rn(v.z);
            __nv_bfloat16 hw = __float2bfloat16_rn(v.w);
            ahi[2 * idx]     = __nv_bfloat162{hx, hy};
            ahi[2 * idx + 1] = __nv_bfloat162{hz, hw};
            alo[2 * idx] = __nv_bfloat162{
                __float2bfloat16_rn(v.x - __bfloat162float(hx)),
                __float2bfloat16_rn(v.y - __bfloat162float(hy))};
            alo[2 * idx + 1] = __nv_bfloat162{
                __float2bfloat16_rn(v.z - __bfloat162float(hz)),
                __float2bfloat16_rn(v.w - __bfloat162float(hw))};
        }
    }
}

// ---------------- conv2 (f32x2), fused: BN1-apply on load + writeback, stats on store ----------------
// io_cnn1 holds PRE-BN conv1 output on entry; post-BN+relu values are written back.
// conv2 output (pre-BN x2) goes to out; its per-channel stats go to g_sum/g_sq[64..128).
__global__ __launch_bounds__(256) void conv2_kernel(
    float* __restrict__ io_cnn1, const float* __restrict__ w,
    const float* __restrict__ bias,
    const float* __restrict__ g1, const float* __restrict__ b1,
    float* __restrict__ out)
{
    __shared__ float sx[32 * L_LEN + 64];
    __shared__ float swT[64 * 64];
    __shared__ float sb[64], ssc[64], ssh[64];
    int n = blockIdx.x, t = threadIdx.x;
    for (int i = t; i < 64 * 64; i += 256) {
        int o = i >> 6, c = i & 63;
        swT[c * 64 + o] = w[i];
    }
    if (t < 64) {
        sb[t] = bias[t];
        sx[32 * L_LEN + t] = 0.f;
        const float invc = 1.0f / ((float)N_NODES * L_LEN);
        float m   = g_sum[t] * invc;
        float var = g_sq[t] * invc - m * m;
        float sc  = rsqrtf(var + EPS) * g1[t];
        ssc[t] = sc;
        ssh[t] = b1[t] - m * sc;
    }
    int tx = t & 15, ty = t >> 4;
    unsigned int sx_base = smem_u32(sx) + tx * 16;

    ull acc[3][4][2];
#pragma unroll
    for (int a = 0; a < 3; a++)
#pragma unroll
        for (int j = 0; j < 4; j++) { acc[a][j][0] = 0ull; acc[a][j][1] = 0ull; }

    for (int cp = 0; cp < 2; cp++) {
        __syncthreads();
        for (int i = t; i < 32 * L_LEN; i += 256) {
            int ch = cp * 32 + i / L_LEN;
            size_t gidx = (size_t)n * IN_FEATS + cp * 32 * L_LEN + i;
            float raw = io_cnn1[gidx];
            float v = fmaxf(raw * ssc[ch] + ssh[ch], 0.f);
            sx[i] = v;
            io_cnn1[gidx] = v;      // post-BN cnn1 output
        }
        __syncthreads();
#pragma unroll 4
        for (int cc = 0; cc < 32; cc++) {
            float wv[4];
            *(float4*)wv = *(const float4*)&swT[(cp * 32 + cc) * 64 + ty * 4];
            ull w2[4];
#pragma unroll
            for (int j = 0; j < 4; j++) w2[j] = pkdup(wv[j]);
#pragma unroll
            for (int lp = 0; lp < 3; lp++) {
                ull x0, x1;
                lds2w(x0, x1, sx_base + cc * (L_LEN * 4) + lp * 256);
#pragma unroll
                for (int j = 0; j < 4; j++) {
                    ffma2(acc[lp][j][0], w2[j], x0);
                    ffma2(acc[lp][j][1], w2[j], x1);
                }
            }
        }
    }
    // store + per-channel stats partials
    float ts[4] = {0.f, 0.f, 0.f, 0.f}, tq[4] = {0.f, 0.f, 0.f, 0.f};
#pragma unroll
    for (int lp = 0; lp < 3; lp++) {
        int l0 = lp * 64 + tx * 4;
        if (l0 >= L_LEN) continue;     // only lp==2, tx>=3
#pragma unroll
        for (int j = 0; j < 4; j++) {
            int o = ty * 4 + j;
            float4 v;
            unpk(acc[lp][j][0], v.x, v.y);
            unpk(acc[lp][j][1], v.z, v.w);
            v.x += sb[o]; v.y += sb[o]; v.z += sb[o]; v.w += sb[o];
            *(float4*)&out[(size_t)n * IN_FEATS + o * L_LEN + l0] = v;
            ts[j] += v.x + v.y + v.z + v.w;
            tq[j] += v.x * v.x + v.y * v.y + v.z * v.z + v.w * v.w;
        }
    }
#pragma unroll
    for (int j = 0; j < 4; j++) {
#pragma unroll
        for (int o = 8; o > 0; o >>= 1) {
            ts[j] += __shfl_xor_sync(0xffffffffu, ts[j], o);
            tq[j] += __shfl_xor_sync(0xffffffffu, tq[j], o);
        }
    }
    if (tx == 0) {
#pragma unroll
        for (int j = 0; j < 4; j++) {
            atomicAdd(&g_sum[64 + ty * 4 + j], ts[j]);
            atomicAdd(&g_sq [64 + ty * 4 + j], tq[j]);
        }
    }
}

// ---------------- degree / CSR ----------------
__global__ void deg_kernel(const int* __restrict__ edges) {
    int e = blockIdx.x * blockDim.x + threadIdx.x;
    if (e < N_EDGES) atomicAdd(&g_deg[edges[2 * e + 1]], 1);
}

__global__ __launch_bounds__(1024) void scan_kernel() {
    __shared__ int s[1024];
    const int CHUNK = 10;
    int t = threadIdx.x;
    int base = t * CHUNK;
    int loc[CHUNK];
    int sum = 0;
#pragma unroll
    for (int i = 0; i < CHUNK; i++) {
        int v = (base + i < N_NODES) ? g_deg[base + i] : 0;
        loc[i] = sum; sum += v;
    }
    s[t] = sum;
    __syncthreads();
    for (int d = 1; d < 1024; d <<= 1) {
        int v = (t >= d) ? s[t - d] : 0;
        __syncthreads();
        s[t] += v;
        __syncthreads();
    }
    int prev = t ? s[t - 1] : 0;
#pragma unroll
    for (int i = 0; i < CHUNK; i++) {
        int n = base + i;
        if (n < N_NODES) {
            int o = prev + loc[i];
            g_off[n] = o; g_pos[n] = o;
            g_denom[n] = (float)max(g_deg[n], 1);
        }
    }
    if (t == 1023) g_off[N_NODES] = s[1023];
}

__global__ void csr_fill_kernel(const int* __restrict__ edges) {
    int e = blockIdx.x * blockDim.x + threadIdx.x;
    if (e < N_EDGES) {
        int sN = edges[2 * e], d = edges[2 * e + 1];
        int idx = atomicAdd(&g_pos[d], 1);
        g_csr[idx] = sN;
    }
}

// ---------------- weight transpose + bf16 split: W[K][256]x2 -> Wcat^T[512][K] ----------------
__global__ void wsplit_kernel(const float* __restrict__ ws, const float* __restrict__ wn,
                              __nv_bfloat16* __restrict__ whi,
                              __nv_bfloat16* __restrict__ wlo, int K)
{
    __shared__ float tile[32][33];
    int k0 = blockIdx.x * 32, n0 = blockIdx.y * 32;
    int tx = threadIdx.x, ty = threadIdx.y;   // 32 x 8
#pragma unroll
    for (int r = 0; r < 32; r += 8) {
        int k = k0 + ty + r, n = n0 + tx;
        float v = (n < 256) ? ws[(size_t)k * 256 + n] : wn[(size_t)k * 256 + n - 256];
        tile[ty + r][tx] = v;
    }
    __syncthreads();
#pragma unroll
    for (int r = 0; r < 32; r += 8) {
        int n = n0 + ty + r, k = k0 + tx;
        float v = tile[tx][ty + r];
        __nv_bfloat16 h = __float2bfloat16_rn(v);
        whi[(size_t)n * K + k] = h;
        wlo[(size_t)n * K + k] = __float2bfloat16_rn(v - __bfloat162float(h));
    }
}

// ---------------- HMMA bf16 split GEMM (3-stage cp.async pipeline) ----------------
// CTA tile 128(M)x128(N), K-chunks of 32.
// Grid (4, 79): blockIdx.x picks 128-col slice of the 512-wide [ws | wn] weight.
// SMEM: row stride 64B (32 bf16), 16B-chunk XOR swizzle: chunk ^ ((row>>1)&3).
__device__ __forceinline__ unsigned int swz(unsigned int base, int row, int kc) {
    return base + row * 64 + ((kc ^ ((row >> 1) & 3)) << 4);
}

__device__ __forceinline__ void mma_issue_load(
    const __nv_bfloat16* __restrict__ Ap, const __nv_bfloat16* __restrict__ Bp,
    unsigned int sa, unsigned int sb, int m0, int n0, int k0, int K, int tid)
{
#pragma unroll
    for (int i = 0; i < 2; i++) {
        int idx = tid + i * 256;
        int row = idx >> 2, cch = idx & 3;
        int rg = m0 + row; if (rg > N_NODES - 1) rg = N_NODES - 1;
        CP16(swz(sa, row, cch), Ap + (size_t)rg * K + k0 + cch * 8);
    }
#pragma unroll
    for (int i = 0; i < 2; i++) {
        int idx = tid + i * 256;
        int row = idx >> 2, cch = idx & 3;
        CP16(swz(sb, row, cch), Bp + (size_t)(n0 + row) * K + k0 + cch * 8);
    }
    asm volatile("cp.async.commit_group;");
}

__global__ __launch_bounds__(256, 2) void gemm_mma_kernel(
    const __nv_bfloat16* __restrict__ Ahi, const __nv_bfloat16* __restrict__ Alo,
    const __nv_bfloat16* __restrict__ Bhi, const __nv_bfloat16* __restrict__ Blo,
    float* __restrict__ Cs, float* __restrict__ Cn, int K)
{
    __shared__ __align__(1024) char AsBuf[3][8192];
    __shared__ __align__(1024) char BsBuf[3][8192];
    int tid = threadIdx.x, wid = tid >> 5, lane = tid & 31;
    int m0 = blockIdx.y * 128;
    int n0 = blockIdx.x * 128;         // 0..384 within [ws|wn]
    int wm = (wid & 3) * 32;
    int wn = (wid >> 2) * 64;

    unsigned int sa[3] = { smem_u32(AsBuf[0]), smem_u32(AsBuf[1]), smem_u32(AsBuf[2]) };
    unsigned int sb[3] = { smem_u32(BsBuf[0]), smem_u32(BsBuf[1]), smem_u32(BsBuf[2]) };

    const __nv_bfloat16* At[3] = {Ahi, Ahi, Alo};
    const __nv_bfloat16* Bt[3] = {Bhi, Blo, Bhi};
    const int KC = K / 32, NC = 3 * KC;   // NC >= 24 always

    float acc[2][8][4];
#pragma unroll
    for (int i = 0; i < 2; i++)
#pragma unroll
        for (int j = 0; j < 8; j++)
#pragma unroll
            for (int q = 0; q < 4; q++) acc[i][j][q] = 0.f;

    // prologue: chunks 0, 1
    mma_issue_load(At[0], Bt[0], sa[0], sb[0], m0, n0, 0, K, tid);
    {
        int t1 = 1 / KC;
        int k1 = (1 - t1 * KC) * 32;
        mma_issue_load(At[t1], Bt[t1], sa[1], sb[1], m0, n0, k1, K, tid);
    }

    for (int c = 0; c < NC; c++) {
        if (c < NC - 1) asm volatile("cp.async.wait_group 1;");
        else            asm volatile("cp.async.wait_group 0;");
        __syncthreads();
        // prefetch chunk c+2 (stage (c+2)%3 was fully consumed at iter c-1)
        if (c + 2 < NC) {
            int t2 = (c + 2) / KC;
            int k2 = ((c + 2) - t2 * KC) * 32;
            int s2 = (c + 2) % 3;
            mma_issue_load(At[t2], Bt[t2], sa[s2], sb[s2], m0, n0, k2, K, tid);
        }
        int s = c % 3;
        unsigned int sas = sa[s], sbs = sb[s];
#pragma unroll
        for (int ks = 0; ks < 2; ks++) {
            int kc = ks * 2 + (lane >> 4);
            unsigned int a[2][4], b[4][4];
            LDSM4(a[0], swz(sas, wm + (lane & 15), kc));
            LDSM4(a[1], swz(sas, wm + 16 + (lane & 15), kc));
#pragma unroll
            for (int j = 0; j < 4; j++)
                LDSM4(b[j], swz(sbs, wn + j * 16 + (lane & 15), kc));
#pragma unroll
            for (int mi = 0; mi < 2; mi++)
#pragma unroll
                for (int j = 0; j < 4; j++) {
                    MMA16816(acc[mi][2 * j],     a[mi], b[j][0], b[j][2]);
                    MMA16816(acc[mi][2 * j + 1], a[mi], b[j][1], b[j][3]);
                }
        }
    }

    // epilogue
    float* Cout = (n0 < 256) ? Cs : Cn;
    int ncol0 = n0 & 255;
    int g = lane >> 2, tq = lane & 3;
#pragma unroll
    for (int mi = 0; mi < 2; mi++) {
        int r0 = m0 + wm + mi * 16 + g;
#pragma unroll
        for (int j = 0; j < 8; j++) {
            int col = ncol0 + wn + j * 8 + tq * 2;
            if (r0 < N_NODES)
                *(float2*)&Cout[(size_t)r0 * 256 + col] =
                    make_float2(acc[mi][j][0], acc[mi][j][1]);
            if (r0 + 8 < N_NODES)
                *(float2*)&Cout[(size_t)(r0 + 8) * 256 + col] =
                    make_float2(acc[mi][j][2], acc[mi][j][3]);
        }
    }
}

// ---------------- fp32 SIMT GEMM (MLP head only) ----------------
__global__ __launch_bounds__(256, 2) void gemm2_kernel(
    const float* __restrict__ A,
    const float* __restrict__ B0, const float* __restrict__ B1,
    float* __restrict__ C0, float* __restrict__ C1,
    int M, int Nc, int K, int nxHalf)
{
    __shared__ float As[8][264];
    __shared__ float Bs[8][132];
    int bx = blockIdx.x;
    const float* B = B0;
    float* C = C0;
    if (bx >= nxHalf) { B = B1; C = C1; bx -= nxHalf; }
    int tid = threadIdx.x;
    int m0 = blockIdx.y * 128, n0 = bx * 128;
    int tx = tid & 15, ty = tid >> 4;

    ull acc[8][4];
#pragma unroll
    for (int i = 0; i < 8; i++)
#pragma unroll
        for (int j = 0; j < 4; j++) acc[i][j] = 0ull;

    int a_row = tid >> 1, a_col = (tid & 1) * 4;
    int b_row = tid >> 5, b_col = (tid & 31) * 4;
    bool a_ok = (m0 + a_row) < M;
    bool b_ok = (n0 + b_col) < Nc;
    const float* Abase = A + (size_t)(m0 + a_row) * K + a_col;
    const float* Bbase = B + n0 + b_col;

    unsigned int as0 = smem_u32(As);
    unsigned int bs0 = smem_u32(Bs);
    unsigned int as_w = as0 + a_col * (264 * 4) + a_row * 8;
    unsigned int as_r = as0 + ty * 32;
    unsigned int bs_r = bs0 + tx * 16;

    for (int k0 = 0; k0 < K; k0 += 8) {
        float4 av = a_ok ? *(const float4*)(Abase + k0) : make_float4(0, 0, 0, 0);
        float4 bv = b_ok ? *(const float4*)(Bbase + (size_t)(k0 + b_row) * Nc)
                         : make_float4(0, 0, 0, 0);
        __syncthreads();
        sts64(as_w + 0 * 1056, pkdup(av.x));
        sts64(as_w + 1 * 1056, pkdup(av.y));
        sts64(as_w + 2 * 1056, pkdup(av.z));
        sts64(as_w + 3 * 1056, pkdup(av.w));
        *(float4*)&Bs[b_row][b_col] = bv;
        __syncthreads();
#pragma unroll
        for (int kk = 0; kk < 8; kk++) {
            ull a2[8], b2[4];
            unsigned int ar = as_r + kk * 1056;
            unsigned int br = bs_r + kk * 528;
            lds2w(a2[0], a2[1], ar);
            lds2w(a2[2], a2[3], ar + 16);
            lds2w(a2[4], a2[5], ar + 512);
            lds2w(a2[6], a2[7], ar + 528);
            lds2w(b2[0], b2[1], br);
            lds2w(b2[2], b2[3], br + 256);
#pragma unroll
            for (int i = 0; i < 8; i++)
#pragma unroll
                for (int j = 0; j < 4; j++) ffma2(acc[i][j], a2[i], b2[j]);
        }
    }
#pragma unroll
    for (int bi = 0; bi < 2; bi++)
#pragma unroll
        for (int i = 0; i < 4; i++) {
            int r = m0 + bi * 64 + ty * 4 + i;
            if (r >= M) continue;
            int i8 = bi * 4 + i;
#pragma unroll
            for (int bj = 0; bj < 2; bj++) {
                int c = n0 + bj * 64 + tx * 4;
                if (c >= Nc) continue;
                float4 v;
                unpk(acc[i8][2 * bj + 0], v.x, v.y);
                unpk(acc[i8][2 * bj + 1], v.z, v.w);
                *(float4*)&C[(size_t)r * Nc + c] = v;
            }
        }
}

// ---------------- neighbor gather (CSR) + combine ----------------
__global__ __launch_bounds__(256) void neigh_combine_kernel(
    const float* __restrict__ hn, const float* __restrict__ hs,
    const float* __restrict__ bias, float* __restrict__ h2)
{
    int n = blockIdx.x, t = threadIdx.x;
    __shared__ int sidx[256];
    int s0 = g_off[n], s1 = g_off[n + 1];
    float acc = 0.f;
    for (int base = s0; base < s1; base += 256) {
        int cnt = min(256, s1 - base);
        __syncthreads();
        if (t < cnt) sidx[t] = g_csr[base + t];
        __syncthreads();
        for (int j = 0; j < cnt; j++) acc += hn[(size_t)sidx[j] * HID + t];
    }
    h2[(size_t)n * HID + t] = hs[(size_t)n * HID + t] + acc / g_denom[n] + bias[t];
}

// ---------------- per-column stats ----------------
__global__ void col_stats_kernel(const float* __restrict__ x, int rows) {
    int c = threadIdx.x, cols = blockDim.x;
    float s = 0.f, q = 0.f;
    for (int r = blockIdx.x; r < rows; r += gridDim.x) {
        float v = x[(size_t)r * cols + c];
        s += v; q += v * v;
    }
    atomicAdd(&g_sum[c], s);
    atomicAdd(&g_sq[c],  q);
}

// ---------------- node BN + residual + relu; optional bf16 split out ----------------
__global__ void bn_apply_kernel(
    const float* __restrict__ x, const float* __restrict__ pre,
    float* __restrict__ outp, float* __restrict__ aux,
    const float* __restrict__ gam, const float* __restrict__ bet,
    __nv_bfloat16* __restrict__ ahi, __nv_bfloat16* __restrict__ alo)
{
    const float invn = 1.0f / (float)N_NODES;
    int total = N_NODES * HID;
    for (int idx = blockIdx.x * blockDim.x + threadIdx.x; idx < total;
         idx += gridDim.x * blockDim.x) {
        int c = idx & (HID - 1);
        float m   = g_sum[c] * invn;
        float var = g_sq[c] * invn - m * m;
        float v = (x[idx] - m) * rsqrtf(var + EPS) * gam[c] + bet[c];
        if (pre) v += pre[idx];
        v = fmaxf(v, 0.f);
        outp[idx] = v;
        if (aux) aux[idx] = v;
        if (ahi) {
            __nv_bfloat16 h = __float2bfloat16_rn(v);
            ahi[idx] = h;
            alo[idx] = __float2bfloat16_rn(v - __bfloat162float(h));
        }
    }
}

// ---------------- MLP head ----------------
__global__ __launch_bounds__(128) void mlp_out_kernel(
    const float* __restrict__ z, const float* __restrict__ gam,
    const float* __restrict__ bet, const float* __restrict__ w2,
    const float* __restrict__ b2, float* __restrict__ out)
{
    __shared__ float sm[64], si[64], sg[64], sb[64], sw[128], sb2[2];
    int t = threadIdx.x;
    if (t < 64) {
        float m   = g_sum[t] / (float)N_NODES;
        float var = g_sq[t] / (float)N_NODES - m * m;
        sm[t] = m;
        si[t] = rsqrtf(var + EPS);
        sg[t] = gam[t];
        sb[t] = bet[t];
    }
    if (t < 128) sw[t] = w2[t];
    if (t < 2)   sb2[t] = b2[t];
    __syncthreads();
    int n = blockIdx.x * 128 + t;
    if (n < N_NODES) {
        float a0 = sb2[0], a1 = sb2[1];
        const float* zr = z + (size_t)n * 64;
#pragma unroll
        for (int j = 0; j < 64; j++) {
            float v = (zr[j] - sm[j]) * si[j] * sg[j] + sb[j];
            v = fmaxf(v, 0.f);
            a0 += v * sw[2 * j];
            a1 += v * sw[2 * j + 1];
        }
        out[2 * n]     = a0;
        out[2 * n + 1] = a1;
    }
}

// ---------------- host ----------------
extern "C" void kernel_launch(void* const* d_in, const int* in_sizes, int n_in,
                              void* d_out, int out_size)
{
    const float* inputs  = (const float*)d_in[0];
    const float* conv1_w = (const float*)d_in[1];
    const float* conv1_b = (const float*)d_in[2];
    const float* bn_c1_g = (const float*)d_in[3];
    const float* bn_c1_b = (const float*)d_in[4];
    const float* conv2_w = (const float*)d_in[5];
    const float* conv2_b = (const float*)d_in[6];
    const float* bn_c2_g = (const float*)d_in[7];
    const float* bn_c2_b = (const float*)d_in[8];
    const float* ws0     = (const float*)d_in[9];
    const float* wn0     = (const float*)d_in[10];
    const float* b0      = (const float*)d_in[11];
    const float* ws_rest = (const float*)d_in[12];
    const float* wn_rest = (const float*)d_in[13];
    const float* b_rest  = (const float*)d_in[14];
    const float* bn_g    = (const float*)d_in[15];
    const float* bn_b    = (const float*)d_in[16];
    const float* mlp_w1  = (const float*)d_in[17];
    // d_in[18] = mlp_b1 : constant shift, cancels exactly inside batchnorm
    const float* mlp_bn_g = (const float*)d_in[19];
    const float* mlp_bn_b = (const float*)d_in[20];
    const float* mlp_w2   = (const float*)d_in[21];
    const float* mlp_b2   = (const float*)d_in[22];
    const int*   edges    = (const int*)d_in[23];

    float* out  = (float*)d_out;
    float* cnn1 = out + CNN1_OFF;
    float* cnn2 = out + CNN2_OFF;
    float* fin  = out + FIN_OFF;

    float *hb, *h2b, *hnb, *hsb, *zb;
    __nv_bfloat16 *ahib, *alob, *whib, *wlob;
    cudaGetSymbolAddress((void**)&hb,   g_h);
    cudaGetSymbolAddress((void**)&h2b,  g_h2);
    cudaGetSymbolAddress((void**)&hnb,  g_hn);
    cudaGetSymbolAddress((void**)&hsb,  g_hs);
    cudaGetSymbolAddress((void**)&zb,   g_z);
    cudaGetSymbolAddress((void**)&ahib, g_Ahi);
    cudaGetSymbolAddress((void**)&alob, g_Alo);
    cudaGetSymbolAddress((void**)&whib, g_Whi);
    cudaGetSymbolAddress((void**)&wlob, g_Wlo);

    // ---- weight transpose + split ----
    wsplit_kernel<<<dim3(IN_FEATS / 32, 16), dim3(32, 8)>>>(ws0, wn0, whib, wlob, IN_FEATS);
    for (int l = 1; l < 4; l++) {
        wsplit_kernel<<<dim3(HID / 32, 16), dim3(32, 8)>>>(
            ws_rest + (size_t)(l - 1) * HID * HID,
            wn_rest + (size_t)(l - 1) * HID * HID,
            whib + W_L0_ELEMS + (size_t)(l - 1) * W_REST_ELEMS,
            wlob + W_L0_ELEMS + (size_t)(l - 1) * W_REST_ELEMS, HID);
    }

    // ---- CNN front-end ----
    // stats layout: conv1 stats at g_sum[0..64), conv2 stats at g_sum[64..128)
    zero_stats_kernel<<<1, 256>>>();
    conv1_kernel<<<N_NODES, 256>>>(inputs, conv1_w, conv1_b, cnn1);   // pre-BN conv1
    chan_stats_kernel<<<2048, 256>>>(cnn1);                           // -> [0..64)
    // conv2: applies BN1+relu inline (writes post-BN cnn1 back), computes x2 + its stats
    conv2_kernel<<<N_NODES, 256>>>(cnn1, conv2_w, conv2_b, bn_c1_g, bn_c1_b, cnn2);
    bn_chan_apply_kernel<<<8192, 256>>>((float4*)cnn2, (const float4*)cnn1,
                                        bn_c2_g, bn_c2_b,
                                        (__nv_bfloat162*)ahib, (__nv_bfloat162*)alob, 64);

    // ---- degree + CSR ----
    zero_deg_kernel<<<(N_NODES + 255) / 256, 256>>>();
    deg_kernel<<<(N_EDGES + 255) / 256, 256>>>(edges);
    scan_kernel<<<1, 1024>>>();
    csr_fill_kernel<<<(N_EDGES + 255) / 256, 256>>>(edges);

    // ---- 4 GraphSAGE layers (HMMA split-bf16 GEMMs) ----
    for (int l = 0; l < 4; l++) {
        int K = (l == 0) ? IN_FEATS : HID;
        const __nv_bfloat16* wh =
            whib + ((l == 0) ? 0 : W_L0_ELEMS + (size_t)(l - 1) * W_REST_ELEMS);
        const __nv_bfloat16* wl =
            wlob + ((l == 0) ? 0 : W_L0_ELEMS + (size_t)(l - 1) * W_REST_ELEMS);
        const float* bb = (l == 0) ? b0 : b_rest + (size_t)(l - 1) * HID;

        gemm_mma_kernel<<<dim3(4, 79), 256>>>(ahib, alob, wh, wl, hsb, hnb, K);

        neigh_combine_kernel<<<N_NODES, 256>>>(hnb, hsb, bb, h2b);

        zero_stats_kernel<<<1, 256>>>();
        col_stats_kernel<<<512, HID>>>(h2b, N_NODES);
        bn_apply_kernel<<<2560, 256>>>(
            h2b, (l > 0) ? hb : nullptr, hb, (l == 3) ? fin : nullptr,
            bn_g + (size_t)l * HID, bn_b + (size_t)l * HID,
            (l < 3) ? ahib : nullptr, (l < 3) ? alob : nullptr);
    }

    // ---- MLP head ----
    {
        dim3 grid(1, 79);
        gemm2_kernel<<<grid, 256>>>(hb, mlp_w1, mlp_w1, zb, zb, N_NODES, C_MID, HID, 1);
        zero_stats_kernel<<<1, 256>>>();
        col_stats_kernel<<<2048, C_MID>>>(zb, N_NODES);
        mlp_out_kernel<<<(N_NODES + 127) / 128, 128>>>(
            zb, mlp_bn_g, mlp_bn_b, mlp_w2, mlp_b2, out);
    }
}